// round 6
// baseline (speedup 1.0000x reference)
#include <cuda_runtime.h>
#include <cuda_bf16.h>
#include <math.h>

#define NN 32768
#define EE 262144
#define FF 64
#define ZZ 10
#define NBB 8
#define LL 2
#define HH 16
#define EPS_SC 0.24253562503633297f  /* 1/sqrt(17) */

// ---------------- scratch (static device globals; no allocation) -------------
__device__ float  g_s0[NN * FF];
__device__ float  g_s1[NN * FF];
__device__ float  g_v0[NN * 3 * FF];            // [n][k][f], layer-0 output v
__device__ float4 g_agg[NN * FF];               // (s, vx, vy, vz) per (n,f)
__device__ float4 g_rbf4[EE * 2];               // bessel basis, 2x float4 per edge
__device__ float4 g_Y4[EE];                     // unit vector (w unused)

// ---------------- zero the aggregation buffer ---------------------------------
__global__ void zero_agg_kernel()
{
    int i = blockIdx.x * blockDim.x + threadIdx.x;   // NN*FF float4 slots
    if (i < NN * FF) g_agg[i] = make_float4(0.f, 0.f, 0.f, 0.f);
}

// ---------------- per-edge radial basis + unit vector (layer invariant) ------
__global__ void precompute_kernel(const float* __restrict__ vectors)
{
    int e = blockIdx.x * blockDim.x + threadIdx.x;
    if (e >= EE) return;
    float x = vectors[e * 3 + 0];
    float y = vectors[e * 3 + 1];
    float z = vectors[e * 3 + 2];
    float r2 = x * x + y * y + z * z + 1e-12f;
    float r  = sqrtf(r2);
    float inv = 1.0f / r;
    g_Y4[e] = make_float4(x * inv, y * inv, z * inv, 0.f);
    float rc = fmaxf(r, 1e-6f);
    float r6 = r2 * r2 * r2;
    float env = 1.0f - 28.0f * r6 + 48.0f * r6 * r - 21.0f * r6 * r2;  // p=6 envelope
    if (r >= 1.0f) env = 0.0f;
    float kk = env * 1.4142135623730951f / rc;
    float pr = 3.14159265358979323846f * rc;
    float rb[NBB];
#pragma unroll
    for (int n = 1; n <= NBB; n++)
        rb[n - 1] = kk * sinf((float)n * pr);
    g_rbf4[e * 2 + 0] = make_float4(rb[0], rb[1], rb[2], rb[3]);
    g_rbf4[e * 2 + 1] = make_float4(rb[4], rb[5], rb[6], rb[7]);
}

// ---------------- node embedding init ----------------------------------------
__global__ void init_kernel(const float* __restrict__ embed_s,
                            const int* __restrict__ spec)
{
    int i = blockIdx.x * blockDim.x + threadIdx.x;  // N*F threads
    int n = i >> 6;
    int f = i & 63;
    g_s0[i] = embed_s[spec[n] * FF + f];
}

// ---------------- edge kernel: CG tensor product + v4 scatter-add -------------
// Radial MLP weights are register-resident: each thread's f is fixed, so its
// 40 (layer1) / 16 (layer0) weights never change across edges.
template <int ITER>
__global__ void __launch_bounds__(256)
edge_kernel(const float* __restrict__ Wr_i,  // [8,320] for this layer
            const int* __restrict__ senders, const int* __restrict__ receivers)
{
    const float* s = (ITER == 0) ? g_s0 : g_s1;
    const float* v = g_v0;   // only used when ITER==1

    int grp = threadIdx.x >> 6;   // 4 edge-groups per block
    int f   = threadIdx.x & 63;
    int stride = gridDim.x * 4;

    // register-cache radial weights for this thread's f
    float wr0[NBB], wr1[NBB], wr2[NBB], wr3[NBB], wr4[NBB];
#pragma unroll
    for (int b = 0; b < NBB; b++) {
        const float* wr = Wr_i + b * 320;
        wr0[b] = wr[f];
        wr2[b] = wr[128 + f];
        if (ITER > 0) {
            wr1[b] = wr[64 + f];
            wr3[b] = wr[192 + f];
            wr4[b] = wr[256 + f];
        }
    }

    for (int e = blockIdx.x * 4 + grp; e < EE; e += stride) {
        int snd = senders[e];
        int rcv = receivers[e];
        float4 yv  = g_Y4[e];
        float4 rba = g_rbf4[e * 2 + 0];
        float4 rbb = g_rbf4[e * 2 + 1];
        float rb[NBB] = {rba.x, rba.y, rba.z, rba.w, rbb.x, rbb.y, rbb.z, rbb.w};

        float w0 = 0.f, w1 = 0.f, w2 = 0.f, w3 = 0.f, w4 = 0.f;
#pragma unroll
        for (int b = 0; b < NBB; b++) {
            w0 = fmaf(rb[b], wr0[b], w0);
            w2 = fmaf(rb[b], wr2[b], w2);
            if (ITER > 0) {
                w1 = fmaf(rb[b], wr1[b], w1);
                w3 = fmaf(rb[b], wr3[b], w3);
                w4 = fmaf(rb[b], wr4[b], w4);
            }
        }

        float ss = s[snd * FF + f];
        float m0, m10, m11, m12;
        if (ITER == 0) {
            m0  = w0 * ss;
            float w2s = w2 * ss;
            m10 = w2s * yv.x; m11 = w2s * yv.y; m12 = w2s * yv.z;
        } else {
            const float* vb = v + snd * 3 * FF;
            float vx = vb[f], vy = vb[64 + f], vz = vb[128 + f];
            float dot = vx * yv.x + vy * yv.y + vz * yv.z;
            m0 = fmaf(w1, dot, w0 * ss);
            float c0 = vy * yv.z - vz * yv.y;
            float c1 = vz * yv.x - vx * yv.z;
            float c2 = vx * yv.y - vy * yv.x;
            float w2s = w2 * ss;
            m10 = fmaf(w2s, yv.x, fmaf(w3, vx, w4 * c0));
            m11 = fmaf(w2s, yv.y, fmaf(w3, vy, w4 * c1));
            m12 = fmaf(w2s, yv.z, fmaf(w3, vz, w4 * c2));
        }
        float4* dst = &g_agg[rcv * FF + f];
        asm volatile("red.global.add.v4.f32 [%0], {%1, %2, %3, %4};"
                     :: "l"(dst), "f"(m0), "f"(m10), "f"(m11), "f"(m12)
                     : "memory");
    }
}

// ---------------- fused node kernel: one warp per node -------------------------
// agg -> (Wls,Wlv) -> product basis -> (Wps,Wpv) (+ per-species skip) -> readout
#define SMEM_NODE ((16384 + 8 * 512) * 4)   /* 80 KB */

template <int ITER>
__global__ void __launch_bounds__(256)
node_kernel(const int* __restrict__ species,
            const float* __restrict__ Wls, const float* __restrict__ Wlv,
            const float* __restrict__ Wps, const float* __restrict__ Wpv,
            const float* __restrict__ skip_s, const float* __restrict__ skip_v,
            const float* __restrict__ pw,     // [Z,9,F] for this layer
            const float* __restrict__ Wread0, const float* __restrict__ Wr1a,
            const float* __restrict__ Wr1b,
            float* __restrict__ out)
{
    extern __shared__ float sm[];
    float* sWls = sm;
    float* sWlv = sm + 4096;
    float* sWps = sm + 8192;
    float* sWpv = sm + 12288;
    float* sStage = sm + 16384;            // 8 warps x 512 floats

    for (int i = threadIdx.x; i < 4096; i += 256) {
        sWls[i] = Wls[i];
        sWlv[i] = Wlv[i];
        sWps[i] = Wps[i];
        sWpv[i] = Wpv[i];
    }
    __syncthreads();

    int wid = threadIdx.x >> 5;            // warp = node slot
    int g2  = threadIdx.x & 31;            // handles outputs 2*g2, 2*g2+1
    int go  = 2 * g2;

    float* stA  = sStage + wid * 512;      // 64:  agg_s / ps
    float* stV  = stA + 64;                // 192: agg_v / pv
    float* stS  = stA + 256;               // 64:  old s (skip input)
    float* stVi = stA + 320;               // 192: old v (skip input)

#pragma unroll 1
    for (int chunk = 0; chunk < 8; chunk++) {
        int n = blockIdx.x * 64 + chunk * 8 + wid;

        // ---- stage inputs (one LDG.128 per output pair) ----
        {
            float4 a0 = g_agg[n * FF + go];
            float4 a1 = g_agg[n * FF + go + 1];
            stA[go]        = a0.x * EPS_SC;  stA[go + 1]        = a1.x * EPS_SC;
            stV[go]        = a0.y * EPS_SC;  stV[go + 1]        = a1.y * EPS_SC;
            stV[64 + go]   = a0.z * EPS_SC;  stV[64 + go + 1]   = a1.z * EPS_SC;
            stV[128 + go]  = a0.w * EPS_SC;  stV[128 + go + 1]  = a1.w * EPS_SC;
        }
        if (ITER > 0) {
            float2 sv = *(const float2*)&g_s1[n * FF + go];
            stS[go] = sv.x; stS[go + 1] = sv.y;
            const float* vb = g_v0 + n * 3 * FF;
            float2 t;
            t = *(const float2*)&vb[go];        stVi[go] = t.x;        stVi[go + 1] = t.y;
            t = *(const float2*)&vb[64 + go];   stVi[64 + go] = t.x;   stVi[64 + go + 1] = t.y;
            t = *(const float2*)&vb[128 + go];  stVi[128 + go] = t.x;  stVi[128 + go + 1] = t.y;
        }
        __syncwarp();

        int spec = species[n];
        const float* sks = skip_s + spec * 4096;
        const float* skv = skip_v + spec * 4096;

        // ---- first matvec pair (+ skip matvecs), f blocked by 4 ----
        float s2a = 0.f, s2b = 0.f;
        float vxa = 0.f, vya = 0.f, vza = 0.f, vxb = 0.f, vyb = 0.f, vzb = 0.f;
        float sca = 0.f, scb = 0.f;
        float ka0 = 0.f, ka1 = 0.f, ka2 = 0.f, kb0 = 0.f, kb1 = 0.f, kb2 = 0.f;
#pragma unroll 4
        for (int f4 = 0; f4 < FF; f4 += 4) {
            float aa[4], xx[4], yy[4], zz[4];
            *(float4*)aa = *(const float4*)&stA[f4];
            *(float4*)xx = *(const float4*)&stV[f4];
            *(float4*)yy = *(const float4*)&stV[64 + f4];
            *(float4*)zz = *(const float4*)&stV[128 + f4];
            float si[4], ux[4], uy[4], uz[4];
            if (ITER > 0) {
                *(float4*)si = *(const float4*)&stS[f4];
                *(float4*)ux = *(const float4*)&stVi[f4];
                *(float4*)uy = *(const float4*)&stVi[64 + f4];
                *(float4*)uz = *(const float4*)&stVi[128 + f4];
            }
#pragma unroll
            for (int j = 0; j < 4; j++) {
                int f = f4 + j;
                float2 wls = *(const float2*)&sWls[f * 64 + go];
                float2 wlv = *(const float2*)&sWlv[f * 64 + go];
                s2a = fmaf(aa[j], wls.x, s2a);  s2b = fmaf(aa[j], wls.y, s2b);
                vxa = fmaf(xx[j], wlv.x, vxa);  vxb = fmaf(xx[j], wlv.y, vxb);
                vya = fmaf(yy[j], wlv.x, vya);  vyb = fmaf(yy[j], wlv.y, vyb);
                vza = fmaf(zz[j], wlv.x, vza);  vzb = fmaf(zz[j], wlv.y, vzb);
                if (ITER > 0) {
                    float2 ws = *(const float2*)&sks[f * 64 + go];
                    float2 wv = *(const float2*)&skv[f * 64 + go];
                    sca = fmaf(si[j], ws.x, sca);  scb = fmaf(si[j], ws.y, scb);
                    ka0 = fmaf(ux[j], wv.x, ka0);  kb0 = fmaf(ux[j], wv.y, kb0);
                    ka1 = fmaf(uy[j], wv.x, ka1);  kb1 = fmaf(uy[j], wv.y, kb1);
                    ka2 = fmaf(uz[j], wv.x, ka2);  kb2 = fmaf(uz[j], wv.y, kb2);
                }
            }
        }

        // ---- product basis ----
        const float* pb = pw + spec * 9 * FF + go;
        float2 p0 = *(const float2*)&pb[0],   p1 = *(const float2*)&pb[64];
        float2 p2 = *(const float2*)&pb[128], p3 = *(const float2*)&pb[192];
        float2 p4 = *(const float2*)&pb[256], p5 = *(const float2*)&pb[320];
        float2 p6 = *(const float2*)&pb[384], p7 = *(const float2*)&pb[448];
        float2 p8 = *(const float2*)&pb[512];

        float vva = vxa * vxa + vya * vya + vza * vza;
        float vvb = vxb * vxb + vyb * vyb + vzb * vzb;
        float sqa = s2a * s2a, sqb = s2b * s2b;
        float psa = p0.x * s2a + p1.x * sqa + p2.x * vva + p3.x * sqa * s2a + p4.x * s2a * vva;
        float psb = p0.y * s2b + p1.y * sqb + p2.y * vvb + p3.y * sqb * s2b + p4.y * s2b * vvb;
        float pca = p5.x + p6.x * s2a + p7.x * sqa + p8.x * vva;
        float pcb = p5.y + p6.y * s2b + p7.y * sqb + p8.y * vvb;

        __syncwarp();
        stA[go] = psa;             stA[go + 1] = psb;
        stV[go] = pca * vxa;       stV[go + 1] = pcb * vxb;
        stV[64 + go] = pca * vya;  stV[64 + go + 1] = pcb * vyb;
        stV[128 + go] = pca * vza; stV[128 + go + 1] = pcb * vzb;
        __syncwarp();

        // ---- second matvec pair (+ skip add), f blocked by 4 ----
        float sna = (ITER > 0) ? sca : 0.f, snb = (ITER > 0) ? scb : 0.f;
        float na0 = (ITER > 0) ? ka0 : 0.f, nb0 = (ITER > 0) ? kb0 : 0.f;
        float na1 = (ITER > 0) ? ka1 : 0.f, nb1 = (ITER > 0) ? kb1 : 0.f;
        float na2 = (ITER > 0) ? ka2 : 0.f, nb2 = (ITER > 0) ? kb2 : 0.f;
#pragma unroll 4
        for (int f4 = 0; f4 < FF; f4 += 4) {
            float aa[4], xx[4], yy[4], zz[4];
            *(float4*)aa = *(const float4*)&stA[f4];
            *(float4*)xx = *(const float4*)&stV[f4];
            *(float4*)yy = *(const float4*)&stV[64 + f4];
            *(float4*)zz = *(const float4*)&stV[128 + f4];
#pragma unroll
            for (int j = 0; j < 4; j++) {
                int f = f4 + j;
                float2 wps = *(const float2*)&sWps[f * 64 + go];
                float2 wpv = *(const float2*)&sWpv[f * 64 + go];
                sna = fmaf(aa[j], wps.x, sna);  snb = fmaf(aa[j], wps.y, snb);
                na0 = fmaf(xx[j], wpv.x, na0);  nb0 = fmaf(xx[j], wpv.y, nb0);
                na1 = fmaf(yy[j], wpv.x, na1);  nb1 = fmaf(yy[j], wpv.y, nb1);
                na2 = fmaf(zz[j], wpv.x, na2);  nb2 = fmaf(zz[j], wpv.y, nb2);
            }
        }

        if (ITER == 0) {
            // next layer needs these
            *(float2*)&g_s1[n * FF + go] = make_float2(sna, snb);
            float* vo = g_v0 + n * 3 * FF;
            *(float2*)&vo[go]       = make_float2(na0, nb0);
            *(float2*)&vo[64 + go]  = make_float2(na1, nb1);
            *(float2*)&vo[128 + go] = make_float2(na2, nb2);

            // linear readout: warp shfl reduction
            float t = sna * Wread0[go] + snb * Wread0[go + 1];
#pragma unroll
            for (int o = 16; o > 0; o >>= 1)
                t += __shfl_xor_sync(0xffffffffu, t, o);
            if (g2 == 0) out[n * LL + 0] = t;
        } else {
            // nonlinear readout: stage s, 16 lanes do hidden layer
            __syncwarp();
            stA[go] = sna; stA[go + 1] = snb;
            __syncwarp();
            float t = 0.f;
            if (g2 < HH) {
                float h = 0.f;
#pragma unroll
                for (int f4 = 0; f4 < FF; f4 += 4) {
                    float aa[4];
                    *(float4*)aa = *(const float4*)&stA[f4];
#pragma unroll
                    for (int j = 0; j < 4; j++)
                        h = fmaf(aa[j], Wr1a[(f4 + j) * HH + g2], h);
                }
                h = h / (1.0f + expf(-h));  // silu
                t = h * Wr1b[g2];
            }
#pragma unroll
            for (int o = 16; o > 0; o >>= 1)
                t += __shfl_xor_sync(0xffffffffu, t, o);
            if (g2 == 0) out[n * LL + 1] = t;
        }
        __syncwarp();
    }
}

// ---------------- host launch -------------------------------------------------
extern "C" void kernel_launch(void* const* d_in, const int* in_sizes, int n_in,
                              void* d_out, int out_size)
{
    const float* vectors  = (const float*)d_in[0];
    const float* embed_s  = (const float*)d_in[1];
    const float* Wr       = (const float*)d_in[2];   // [2,8,320]
    const float* Wls      = (const float*)d_in[3];   // [2,64,64]
    const float* Wlv      = (const float*)d_in[4];
    const float* skip_s   = (const float*)d_in[5];   // [10,64,64]
    const float* skip_v   = (const float*)d_in[6];
    const float* pw       = (const float*)d_in[7];   // [2,10,9,64]
    const float* Wps      = (const float*)d_in[8];
    const float* Wpv      = (const float*)d_in[9];
    const float* Wread0   = (const float*)d_in[10];  // [64,1]
    const float* Wr1a     = (const float*)d_in[11];  // [64,16]
    const float* Wr1b     = (const float*)d_in[12];  // [16,1]
    const int*   senders  = (const int*)d_in[13];
    const int*   receivers= (const int*)d_in[14];
    const int*   species  = (const int*)d_in[15];
    float* out = (float*)d_out;

    static bool attr_done = false;
    if (!attr_done) {
        cudaFuncSetAttribute((const void*)node_kernel<0>,
                             cudaFuncAttributeMaxDynamicSharedMemorySize, SMEM_NODE);
        cudaFuncSetAttribute((const void*)node_kernel<1>,
                             cudaFuncAttributeMaxDynamicSharedMemorySize, SMEM_NODE);
        attr_done = true;
    }

    const int zblocks = (NN * FF + 255) / 256;

    precompute_kernel<<<EE / 256, 256>>>(vectors);
    init_kernel<<<(NN * FF) / 256, 256>>>(embed_s, species);

    // ---- layer 0 ----
    zero_agg_kernel<<<zblocks, 256>>>();
    edge_kernel<0><<<2048, 256>>>(Wr, senders, receivers);
    node_kernel<0><<<NN / 64, 256, SMEM_NODE>>>(
        species, Wls, Wlv, Wps, Wpv, skip_s, skip_v, pw,
        Wread0, Wr1a, Wr1b, out);

    // ---- layer 1 ----
    zero_agg_kernel<<<zblocks, 256>>>();
    edge_kernel<1><<<2048, 256>>>(Wr + NBB * 5 * FF, senders, receivers);
    node_kernel<1><<<NN / 64, 256, SMEM_NODE>>>(
        species,
        Wls + FF * FF, Wlv + FF * FF, Wps + FF * FF, Wpv + FF * FF,
        skip_s, skip_v, pw + ZZ * 9 * FF,
        Wread0, Wr1a, Wr1b, out);
}

// round 7
// speedup vs baseline: 1.0656x; 1.0656x over previous
#include <cuda_runtime.h>
#include <cuda_bf16.h>
#include <math.h>

#define NN 32768
#define EE 262144
#define FF 64
#define ZZ 10
#define NBB 8
#define LL 2
#define HH 16
#define NPAD (NN + 64 * ZZ)              /* species-padded node ordering */
#define EPS_SC 0.24253562503633297f      /* 1/sqrt(17) */

// ---------------- scratch (static device globals; no allocation) -------------
__device__ float  g_s0[NN * FF];
__device__ float  g_s1[NN * FF];
__device__ float  g_v0[NN * 3 * FF];     // [n][k][f]
__device__ float4 g_agg[NN * FF];        // (s, vx, vy, vz) per (n,f)
__device__ float4 g_rbf4s[EE * 2];       // bessel basis, receiver-sorted
__device__ float4 g_Y4s[EE];             // unit vector, receiver-sorted
__device__ int    g_snds[EE];            // senders, receiver-sorted
__device__ int    g_cnt[NN];             // receiver histogram
__device__ int    g_cur[NN];             // scatter cursors
__device__ int    g_off[NN + 1];         // CSR offsets
__device__ int    g_scnt[ZZ];            // species histogram
__device__ int    g_scur[ZZ];
__device__ int    g_norder[NPAD];        // species-grouped node order (-1 pad)

// ---------------- sort phase 1: zero + histograms ------------------------------
__global__ void zero_sort_kernel()
{
    int i = blockIdx.x * blockDim.x + threadIdx.x;
    if (i < NN)   g_cnt[i] = 0;
    if (i < ZZ)   g_scnt[i] = 0;
    if (i < NPAD) g_norder[i] = -1;
}

__global__ void hist_kernel(const int* __restrict__ receivers,
                            const int* __restrict__ species)
{
    int i = blockIdx.x * blockDim.x + threadIdx.x;
    if (i < EE) atomicAdd(&g_cnt[receivers[i]], 1);
    if (i < NN) atomicAdd(&g_scnt[species[i]], 1);
}

// ---------------- sort phase 2: scans ------------------------------------------
__global__ void scan_kernel()   // 1 block, 1024 threads; NN = 1024*32
{
    __shared__ int part[1024];
    int tid = threadIdx.x;
    int base = tid * 32;
    int loc[32];
    int sum = 0;
#pragma unroll
    for (int j = 0; j < 32; j++) { loc[j] = sum; sum += g_cnt[base + j]; }
    part[tid] = sum;
    __syncthreads();
    for (int o = 1; o < 1024; o <<= 1) {
        int v = (tid >= o) ? part[tid - o] : 0;
        __syncthreads();
        part[tid] += v;
        __syncthreads();
    }
    int pref = part[tid] - sum;   // exclusive prefix for this chunk
#pragma unroll
    for (int j = 0; j < 32; j++) {
        int o = pref + loc[j];
        g_off[base + j] = o;
        g_cur[base + j] = o;
    }
    if (tid == 1023) g_off[NN] = part[1023];
}

__global__ void species_scan_kernel()   // 1 thread, Z=10
{
    int off = 0;
    for (int z = 0; z < ZZ; z++) {
        g_scur[z] = off;
        off += ((g_scnt[z] + 63) / 64) * 64;   // pad to block multiple
    }
}

// ---------------- sort phase 3: scatter ----------------------------------------
__global__ void species_scatter_kernel(const int* __restrict__ species)
{
    int n = blockIdx.x * blockDim.x + threadIdx.x;
    if (n >= NN) return;
    int pos = atomicAdd(&g_scur[species[n]], 1);
    g_norder[pos] = n;
}

// precompute bessel + Y and scatter into receiver-sorted slots
__global__ void precompute_kernel(const float* __restrict__ vectors,
                                  const int* __restrict__ senders,
                                  const int* __restrict__ receivers)
{
    int e = blockIdx.x * blockDim.x + threadIdx.x;
    if (e >= EE) return;
    float x = vectors[e * 3 + 0];
    float y = vectors[e * 3 + 1];
    float z = vectors[e * 3 + 2];
    float r2 = x * x + y * y + z * z + 1e-12f;
    float r  = sqrtf(r2);
    float inv = 1.0f / r;
    float rc = fmaxf(r, 1e-6f);
    float r6 = r2 * r2 * r2;
    float env = 1.0f - 28.0f * r6 + 48.0f * r6 * r - 21.0f * r6 * r2;  // p=6 envelope
    if (r >= 1.0f) env = 0.0f;
    float kk = env * 1.4142135623730951f / rc;
    float pr = 3.14159265358979323846f * rc;
    float rb[NBB];
#pragma unroll
    for (int n = 1; n <= NBB; n++)
        rb[n - 1] = kk * __sinf((float)n * pr);

    int pos = atomicAdd(&g_cur[receivers[e]], 1);
    g_Y4s[pos] = make_float4(x * inv, y * inv, z * inv, 0.f);
    g_rbf4s[pos * 2 + 0] = make_float4(rb[0], rb[1], rb[2], rb[3]);
    g_rbf4s[pos * 2 + 1] = make_float4(rb[4], rb[5], rb[6], rb[7]);
    g_snds[pos] = senders[e];
}

// ---------------- node embedding init ----------------------------------------
__global__ void init_kernel(const float* __restrict__ embed_s,
                            const int* __restrict__ spec)
{
    int i = blockIdx.x * blockDim.x + threadIdx.x;  // N*F threads
    int n = i >> 6;
    int f = i & 63;
    g_s0[i] = embed_s[spec[n] * FF + f];
}

// ---------------- fused edge gather + segmented reduction ----------------------
// 64 threads own one receiver node; walk its CSR segment; accumulate in regs;
// ONE coalesced float4 store per (n,f). No atomics.
template <int ITER>
__global__ void __launch_bounds__(256)
edge_agg_kernel(const float* __restrict__ Wr_i)   // [8,320] for this layer
{
    const float* s = (ITER == 0) ? g_s0 : g_s1;
    const float* v = g_v0;

    int slot = threadIdx.x >> 6;
    int f    = threadIdx.x & 63;
    int n    = blockIdx.x * 4 + slot;

    // register-cache radial weights for this thread's f (layer-invariant per edge)
    float wr0[NBB], wr1[NBB], wr2[NBB], wr3[NBB], wr4[NBB];
#pragma unroll
    for (int b = 0; b < NBB; b++) {
        const float* wr = Wr_i + b * 320;
        wr0[b] = wr[f];
        wr2[b] = wr[128 + f];
        if (ITER > 0) {
            wr1[b] = wr[64 + f];
            wr3[b] = wr[192 + f];
            wr4[b] = wr[256 + f];
        }
    }

    int beg = g_off[n], end = g_off[n + 1];
    float a0 = 0.f, a1 = 0.f, a2 = 0.f, a3 = 0.f;

#pragma unroll 2
    for (int i = beg; i < end; i++) {
        int snd = g_snds[i];                     // uniform -> broadcast
        float4 yv  = g_Y4s[i];
        float4 rba = g_rbf4s[i * 2 + 0];
        float4 rbb = g_rbf4s[i * 2 + 1];
        float rb[NBB] = {rba.x, rba.y, rba.z, rba.w, rbb.x, rbb.y, rbb.z, rbb.w};

        float w0 = 0.f, w1 = 0.f, w2 = 0.f, w3 = 0.f, w4 = 0.f;
#pragma unroll
        for (int b = 0; b < NBB; b++) {
            w0 = fmaf(rb[b], wr0[b], w0);
            w2 = fmaf(rb[b], wr2[b], w2);
            if (ITER > 0) {
                w1 = fmaf(rb[b], wr1[b], w1);
                w3 = fmaf(rb[b], wr3[b], w3);
                w4 = fmaf(rb[b], wr4[b], w4);
            }
        }

        float ss = s[snd * FF + f];
        if (ITER == 0) {
            a0 += w0 * ss;
            float w2s = w2 * ss;
            a1 = fmaf(w2s, yv.x, a1);
            a2 = fmaf(w2s, yv.y, a2);
            a3 = fmaf(w2s, yv.z, a3);
        } else {
            const float* vb = v + snd * 3 * FF;
            float vx = vb[f], vy = vb[64 + f], vz = vb[128 + f];
            float dot = vx * yv.x + vy * yv.y + vz * yv.z;
            a0 += fmaf(w1, dot, w0 * ss);
            float c0 = vy * yv.z - vz * yv.y;
            float c1 = vz * yv.x - vx * yv.z;
            float c2 = vx * yv.y - vy * yv.x;
            float w2s = w2 * ss;
            a1 += fmaf(w2s, yv.x, fmaf(w3, vx, w4 * c0));
            a2 += fmaf(w2s, yv.y, fmaf(w3, vy, w4 * c1));
            a3 += fmaf(w2s, yv.z, fmaf(w3, vz, w4 * c2));
        }
    }
    g_agg[n * FF + f] = make_float4(a0, a1, a2, a3);
}

// ---------------- node kernel, layer 0 (no skip) -------------------------------
#define SMEM_NODE0 ((16384 + 8 * 512) * 4)   /* 80 KB */

__global__ void __launch_bounds__(256)
node0_kernel(const float* __restrict__ Wls, const float* __restrict__ Wlv,
             const float* __restrict__ Wps, const float* __restrict__ Wpv,
             const int* __restrict__ species,
             const float* __restrict__ pw,     // [Z,9,F] layer 0
             const float* __restrict__ Wread0,
             float* __restrict__ out)
{
    extern __shared__ float sm[];
    float* sWls = sm;
    float* sWlv = sm + 4096;
    float* sWps = sm + 8192;
    float* sWpv = sm + 12288;
    float* sStage = sm + 16384;            // 8 warps x 512 floats

    for (int i = threadIdx.x; i < 4096; i += 256) {
        sWls[i] = Wls[i];
        sWlv[i] = Wlv[i];
        sWps[i] = Wps[i];
        sWpv[i] = Wpv[i];
    }
    __syncthreads();

    int wid = threadIdx.x >> 5;
    int g2  = threadIdx.x & 31;
    int go  = 2 * g2;

    float* stA = sStage + wid * 512;       // 64:  agg_s / ps
    float* stV = stA + 64;                 // 192: agg_v / pv

#pragma unroll 1
    for (int chunk = 0; chunk < 8; chunk++) {
        int n = blockIdx.x * 64 + chunk * 8 + wid;

        {
            float4 a0 = g_agg[n * FF + go];
            float4 a1 = g_agg[n * FF + go + 1];
            stA[go]       = a0.x * EPS_SC;  stA[go + 1]       = a1.x * EPS_SC;
            stV[go]       = a0.y * EPS_SC;  stV[go + 1]       = a1.y * EPS_SC;
            stV[64 + go]  = a0.z * EPS_SC;  stV[64 + go + 1]  = a1.z * EPS_SC;
            stV[128 + go] = a0.w * EPS_SC;  stV[128 + go + 1] = a1.w * EPS_SC;
        }
        __syncwarp();

        int spec = species[n];

        float s2a = 0.f, s2b = 0.f;
        float vxa = 0.f, vya = 0.f, vza = 0.f, vxb = 0.f, vyb = 0.f, vzb = 0.f;
#pragma unroll 4
        for (int f4 = 0; f4 < FF; f4 += 4) {
            float aa[4], xx[4], yy[4], zz[4];
            *(float4*)aa = *(const float4*)&stA[f4];
            *(float4*)xx = *(const float4*)&stV[f4];
            *(float4*)yy = *(const float4*)&stV[64 + f4];
            *(float4*)zz = *(const float4*)&stV[128 + f4];
#pragma unroll
            for (int j = 0; j < 4; j++) {
                int f = f4 + j;
                float2 wls = *(const float2*)&sWls[f * 64 + go];
                float2 wlv = *(const float2*)&sWlv[f * 64 + go];
                s2a = fmaf(aa[j], wls.x, s2a);  s2b = fmaf(aa[j], wls.y, s2b);
                vxa = fmaf(xx[j], wlv.x, vxa);  vxb = fmaf(xx[j], wlv.y, vxb);
                vya = fmaf(yy[j], wlv.x, vya);  vyb = fmaf(yy[j], wlv.y, vyb);
                vza = fmaf(zz[j], wlv.x, vza);  vzb = fmaf(zz[j], wlv.y, vzb);
            }
        }

        const float* pb = pw + spec * 9 * FF + go;
        float2 p0 = *(const float2*)&pb[0],   p1 = *(const float2*)&pb[64];
        float2 p2 = *(const float2*)&pb[128], p3 = *(const float2*)&pb[192];
        float2 p4 = *(const float2*)&pb[256], p5 = *(const float2*)&pb[320];
        float2 p6 = *(const float2*)&pb[384], p7 = *(const float2*)&pb[448];
        float2 p8 = *(const float2*)&pb[512];

        float vva = vxa * vxa + vya * vya + vza * vza;
        float vvb = vxb * vxb + vyb * vyb + vzb * vzb;
        float sqa = s2a * s2a, sqb = s2b * s2b;
        float psa = p0.x * s2a + p1.x * sqa + p2.x * vva + p3.x * sqa * s2a + p4.x * s2a * vva;
        float psb = p0.y * s2b + p1.y * sqb + p2.y * vvb + p3.y * sqb * s2b + p4.y * s2b * vvb;
        float pca = p5.x + p6.x * s2a + p7.x * sqa + p8.x * vva;
        float pcb = p5.y + p6.y * s2b + p7.y * sqb + p8.y * vvb;

        __syncwarp();
        stA[go] = psa;             stA[go + 1] = psb;
        stV[go] = pca * vxa;       stV[go + 1] = pcb * vxb;
        stV[64 + go] = pca * vya;  stV[64 + go + 1] = pcb * vyb;
        stV[128 + go] = pca * vza; stV[128 + go + 1] = pcb * vzb;
        __syncwarp();

        float sna = 0.f, snb = 0.f;
        float na0 = 0.f, nb0 = 0.f, na1 = 0.f, nb1 = 0.f, na2 = 0.f, nb2 = 0.f;
#pragma unroll 4
        for (int f4 = 0; f4 < FF; f4 += 4) {
            float aa[4], xx[4], yy[4], zz[4];
            *(float4*)aa = *(const float4*)&stA[f4];
            *(float4*)xx = *(const float4*)&stV[f4];
            *(float4*)yy = *(const float4*)&stV[64 + f4];
            *(float4*)zz = *(const float4*)&stV[128 + f4];
#pragma unroll
            for (int j = 0; j < 4; j++) {
                int f = f4 + j;
                float2 wps = *(const float2*)&sWps[f * 64 + go];
                float2 wpv = *(const float2*)&sWpv[f * 64 + go];
                sna = fmaf(aa[j], wps.x, sna);  snb = fmaf(aa[j], wps.y, snb);
                na0 = fmaf(xx[j], wpv.x, na0);  nb0 = fmaf(xx[j], wpv.y, nb0);
                na1 = fmaf(yy[j], wpv.x, na1);  nb1 = fmaf(yy[j], wpv.y, nb1);
                na2 = fmaf(zz[j], wpv.x, na2);  nb2 = fmaf(zz[j], wpv.y, nb2);
            }
        }

        *(float2*)&g_s1[n * FF + go] = make_float2(sna, snb);
        float* vo = g_v0 + n * 3 * FF;
        *(float2*)&vo[go]       = make_float2(na0, nb0);
        *(float2*)&vo[64 + go]  = make_float2(na1, nb1);
        *(float2*)&vo[128 + go] = make_float2(na2, nb2);

        float t = sna * Wread0[go] + snb * Wread0[go + 1];
#pragma unroll
        for (int o = 16; o > 0; o >>= 1)
            t += __shfl_xor_sync(0xffffffffu, t, o);
        if (g2 == 0) out[n * LL + 0] = t;
        __syncwarp();
    }
}

// ---------------- node kernel, layer 1 (species-grouped, skip staged) ----------
#define SMEM_NODE1 ((24576 + 8 * 512) * 4)   /* 112 KB */

__global__ void __launch_bounds__(256)
node1_kernel(const float* __restrict__ Wls, const float* __restrict__ Wlv,
             const float* __restrict__ Wps, const float* __restrict__ Wpv,
             const int* __restrict__ species,
             const float* __restrict__ skip_s, const float* __restrict__ skip_v,
             const float* __restrict__ pw,     // [Z,9,F] layer 1
             const float* __restrict__ Wr1a, const float* __restrict__ Wr1b,
             float* __restrict__ out)
{
    int n0 = g_norder[blockIdx.x * 64];
    if (n0 < 0) return;                    // fully-padded block
    int spec = species[n0];                // uniform for the whole block

    extern __shared__ float sm[];
    float* sWls = sm;
    float* sWlv = sm + 4096;
    float* sWps = sm + 8192;
    float* sWpv = sm + 12288;
    float* sKs  = sm + 16384;              // per-species skip_s
    float* sKv  = sm + 20480;              // per-species skip_v
    float* sStage = sm + 24576;            // 8 warps x 512 floats

    {
        const float* ks = skip_s + spec * 4096;
        const float* kv = skip_v + spec * 4096;
        for (int i = threadIdx.x; i < 4096; i += 256) {
            sWls[i] = Wls[i];
            sWlv[i] = Wlv[i];
            sWps[i] = Wps[i];
            sWpv[i] = Wpv[i];
            sKs[i]  = ks[i];
            sKv[i]  = kv[i];
        }
    }
    __syncthreads();

    int wid = threadIdx.x >> 5;
    int g2  = threadIdx.x & 31;
    int go  = 2 * g2;

    float* stA  = sStage + wid * 512;      // 64:  agg_s / ps
    float* stV  = stA + 64;                // 192: agg_v / pv
    float* stS  = stA + 256;               // 64:  old s (skip input)
    float* stVi = stA + 320;               // 192: old v (skip input)

    const float* pb = pw + spec * 9 * FF + go;
    float2 p0 = *(const float2*)&pb[0],   p1 = *(const float2*)&pb[64];
    float2 p2 = *(const float2*)&pb[128], p3 = *(const float2*)&pb[192];
    float2 p4 = *(const float2*)&pb[256], p5 = *(const float2*)&pb[320];
    float2 p6 = *(const float2*)&pb[384], p7 = *(const float2*)&pb[448];
    float2 p8 = *(const float2*)&pb[512];

#pragma unroll 1
    for (int chunk = 0; chunk < 8; chunk++) {
        int n = g_norder[blockIdx.x * 64 + chunk * 8 + wid];
        if (n >= 0) {
            {
                float4 a0 = g_agg[n * FF + go];
                float4 a1 = g_agg[n * FF + go + 1];
                stA[go]       = a0.x * EPS_SC;  stA[go + 1]       = a1.x * EPS_SC;
                stV[go]       = a0.y * EPS_SC;  stV[go + 1]       = a1.y * EPS_SC;
                stV[64 + go]  = a0.z * EPS_SC;  stV[64 + go + 1]  = a1.z * EPS_SC;
                stV[128 + go] = a0.w * EPS_SC;  stV[128 + go + 1] = a1.w * EPS_SC;
            }
            {
                float2 sv = *(const float2*)&g_s1[n * FF + go];
                stS[go] = sv.x; stS[go + 1] = sv.y;
                const float* vb = g_v0 + n * 3 * FF;
                float2 t;
                t = *(const float2*)&vb[go];       stVi[go] = t.x;       stVi[go + 1] = t.y;
                t = *(const float2*)&vb[64 + go];  stVi[64 + go] = t.x;  stVi[64 + go + 1] = t.y;
                t = *(const float2*)&vb[128 + go]; stVi[128 + go] = t.x; stVi[128 + go + 1] = t.y;
            }
            __syncwarp();

            float s2a = 0.f, s2b = 0.f;
            float vxa = 0.f, vya = 0.f, vza = 0.f, vxb = 0.f, vyb = 0.f, vzb = 0.f;
            float sca = 0.f, scb = 0.f;
            float ka0 = 0.f, ka1 = 0.f, ka2 = 0.f, kb0 = 0.f, kb1 = 0.f, kb2 = 0.f;
#pragma unroll 4
            for (int f4 = 0; f4 < FF; f4 += 4) {
                float aa[4], xx[4], yy[4], zz[4], si[4], ux[4], uy[4], uz[4];
                *(float4*)aa = *(const float4*)&stA[f4];
                *(float4*)xx = *(const float4*)&stV[f4];
                *(float4*)yy = *(const float4*)&stV[64 + f4];
                *(float4*)zz = *(const float4*)&stV[128 + f4];
                *(float4*)si = *(const float4*)&stS[f4];
                *(float4*)ux = *(const float4*)&stVi[f4];
                *(float4*)uy = *(const float4*)&stVi[64 + f4];
                *(float4*)uz = *(const float4*)&stVi[128 + f4];
#pragma unroll
                for (int j = 0; j < 4; j++) {
                    int f = f4 + j;
                    float2 wls = *(const float2*)&sWls[f * 64 + go];
                    float2 wlv = *(const float2*)&sWlv[f * 64 + go];
                    float2 ws  = *(const float2*)&sKs[f * 64 + go];
                    float2 wv  = *(const float2*)&sKv[f * 64 + go];
                    s2a = fmaf(aa[j], wls.x, s2a);  s2b = fmaf(aa[j], wls.y, s2b);
                    vxa = fmaf(xx[j], wlv.x, vxa);  vxb = fmaf(xx[j], wlv.y, vxb);
                    vya = fmaf(yy[j], wlv.x, vya);  vyb = fmaf(yy[j], wlv.y, vyb);
                    vza = fmaf(zz[j], wlv.x, vza);  vzb = fmaf(zz[j], wlv.y, vzb);
                    sca = fmaf(si[j], ws.x, sca);   scb = fmaf(si[j], ws.y, scb);
                    ka0 = fmaf(ux[j], wv.x, ka0);   kb0 = fmaf(ux[j], wv.y, kb0);
                    ka1 = fmaf(uy[j], wv.x, ka1);   kb1 = fmaf(uy[j], wv.y, kb1);
                    ka2 = fmaf(uz[j], wv.x, ka2);   kb2 = fmaf(uz[j], wv.y, kb2);
                }
            }

            float vva = vxa * vxa + vya * vya + vza * vza;
            float vvb = vxb * vxb + vyb * vyb + vzb * vzb;
            float sqa = s2a * s2a, sqb = s2b * s2b;
            float psa = p0.x * s2a + p1.x * sqa + p2.x * vva + p3.x * sqa * s2a + p4.x * s2a * vva;
            float psb = p0.y * s2b + p1.y * sqb + p2.y * vvb + p3.y * sqb * s2b + p4.y * s2b * vvb;
            float pca = p5.x + p6.x * s2a + p7.x * sqa + p8.x * vva;
            float pcb = p5.y + p6.y * s2b + p7.y * sqb + p8.y * vvb;

            __syncwarp();
            stA[go] = psa;             stA[go + 1] = psb;
            stV[go] = pca * vxa;       stV[go + 1] = pcb * vxb;
            stV[64 + go] = pca * vya;  stV[64 + go + 1] = pcb * vyb;
            stV[128 + go] = pca * vza; stV[128 + go + 1] = pcb * vzb;
            __syncwarp();

            float sna = sca, snb = scb;
#pragma unroll 4
            for (int f4 = 0; f4 < FF; f4 += 4) {
                float aa[4];
                *(float4*)aa = *(const float4*)&stA[f4];
#pragma unroll
                for (int j = 0; j < 4; j++) {
                    float2 wps = *(const float2*)&sWps[(f4 + j) * 64 + go];
                    sna = fmaf(aa[j], wps.x, sna);  snb = fmaf(aa[j], wps.y, snb);
                }
            }
            // v output of layer 1 is dead (readout uses s only)

            __syncwarp();
            stA[go] = sna; stA[go + 1] = snb;
            __syncwarp();
            float t = 0.f;
            if (g2 < HH) {
                float h = 0.f;
#pragma unroll
                for (int f4 = 0; f4 < FF; f4 += 4) {
                    float aa[4];
                    *(float4*)aa = *(const float4*)&stA[f4];
#pragma unroll
                    for (int j = 0; j < 4; j++)
                        h = fmaf(aa[j], Wr1a[(f4 + j) * HH + g2], h);
                }
                h = h / (1.0f + expf(-h));  // silu
                t = h * Wr1b[g2];
            }
#pragma unroll
            for (int o = 16; o > 0; o >>= 1)
                t += __shfl_xor_sync(0xffffffffu, t, o);
            if (g2 == 0) out[n * LL + 1] = t;
            __syncwarp();
        }
    }
}

// ---------------- host launch -------------------------------------------------
extern "C" void kernel_launch(void* const* d_in, const int* in_sizes, int n_in,
                              void* d_out, int out_size)
{
    const float* vectors  = (const float*)d_in[0];
    const float* embed_s  = (const float*)d_in[1];
    const float* Wr       = (const float*)d_in[2];   // [2,8,320]
    const float* Wls      = (const float*)d_in[3];   // [2,64,64]
    const float* Wlv      = (const float*)d_in[4];
    const float* skip_s   = (const float*)d_in[5];   // [10,64,64]
    const float* skip_v   = (const float*)d_in[6];
    const float* pw       = (const float*)d_in[7];   // [2,10,9,64]
    const float* Wps      = (const float*)d_in[8];
    const float* Wpv      = (const float*)d_in[9];
    const float* Wread0   = (const float*)d_in[10];  // [64,1]
    const float* Wr1a     = (const float*)d_in[11];  // [64,16]
    const float* Wr1b     = (const float*)d_in[12];  // [16,1]
    const int*   senders  = (const int*)d_in[13];
    const int*   receivers= (const int*)d_in[14];
    const int*   species  = (const int*)d_in[15];
    float* out = (float*)d_out;

    static bool attr_done = false;
    if (!attr_done) {
        cudaFuncSetAttribute((const void*)node0_kernel,
                             cudaFuncAttributeMaxDynamicSharedMemorySize, SMEM_NODE0);
        cudaFuncSetAttribute((const void*)node1_kernel,
                             cudaFuncAttributeMaxDynamicSharedMemorySize, SMEM_NODE1);
        attr_done = true;
    }

    // ---- CSR sorts (receiver CSR + species grouping) ----
    zero_sort_kernel<<<(NPAD + 255) / 256, 256>>>();
    hist_kernel<<<EE / 256, 256>>>(receivers, species);
    scan_kernel<<<1, 1024>>>();
    species_scan_kernel<<<1, 1>>>();
    precompute_kernel<<<EE / 256, 256>>>(vectors, senders, receivers);
    species_scatter_kernel<<<NN / 256, 256>>>(species);
    init_kernel<<<(NN * FF) / 256, 256>>>(embed_s, species);

    // ---- layer 0 ----
    edge_agg_kernel<0><<<NN / 4, 256>>>(Wr);
    node0_kernel<<<NN / 64, 256, SMEM_NODE0>>>(
        Wls, Wlv, Wps, Wpv, species, pw, Wread0, out);

    // ---- layer 1 ----
    edge_agg_kernel<1><<<NN / 4, 256>>>(Wr + NBB * 5 * FF);
    node1_kernel<<<NPAD / 64, 256, SMEM_NODE1>>>(
        Wls + FF * FF, Wlv + FF * FF, Wps + FF * FF, Wpv + FF * FF,
        species, skip_s, skip_v, pw + ZZ * 9 * FF,
        Wr1a, Wr1b, out);
}

// round 8
// speedup vs baseline: 1.1748x; 1.1024x over previous
#include <cuda_runtime.h>
#include <cuda_bf16.h>
#include <math.h>

#define NN 32768
#define EE 262144
#define FF 64
#define ZZ 10
#define NBB 8
#define LL 2
#define HH 16
#define NPAD (NN + 64 * ZZ)              /* species-padded node ordering */
#define EPS_SC 0.24253562503633297f      /* 1/sqrt(17) */

typedef unsigned long long u64;

// ---------------- packed fp32x2 helpers ----------------------------------------
__device__ __forceinline__ u64 pack2(float lo, float hi) {
    u64 r; asm("mov.b64 %0, {%1, %2};" : "=l"(r) : "f"(lo), "f"(hi)); return r;
}
__device__ __forceinline__ u64 bcast2(float v) { return pack2(v, v); }
__device__ __forceinline__ float2 u2f(u64 v) {
    float2 r; asm("mov.b64 {%0, %1}, %2;" : "=f"(r.x), "=f"(r.y) : "l"(v)); return r;
}
__device__ __forceinline__ u64 fma2(u64 a, u64 b, u64 c) {
    u64 r; asm("fma.rn.f32x2 %0, %1, %2, %3;" : "=l"(r) : "l"(a), "l"(b), "l"(c)); return r;
}
__device__ __forceinline__ u64 mul2(u64 a, u64 b) {
    u64 r; asm("mul.rn.f32x2 %0, %1, %2;" : "=l"(r) : "l"(a), "l"(b)); return r;
}

// ---------------- scratch (static device globals; no allocation) -------------
__device__ float  g_s0[NN * FF];
__device__ float  g_s1[NN * FF];
__device__ float  g_v0[NN * 3 * FF];     // [n][k][f]
__device__ float4 g_agg[NN * FF];        // (s, vx, vy, vz) per (n,f)
__device__ float4 g_rbf4s[EE * 2];       // bessel basis, receiver-sorted
__device__ float4 g_Y4s[EE];             // unit vector, receiver-sorted
__device__ int    g_snds[EE];            // senders, receiver-sorted
__device__ int    g_cnt[NN];             // receiver histogram
__device__ int    g_cur[NN];             // scatter cursors
__device__ int    g_off[NN + 1];         // CSR offsets
__device__ int    g_scnt[ZZ];            // species histogram
__device__ int    g_scur[ZZ];
__device__ int    g_norder[NPAD];        // species-grouped node order (-1 pad)

// ---------------- sort phase 1: zero + histograms ------------------------------
__global__ void zero_sort_kernel()
{
    int i = blockIdx.x * blockDim.x + threadIdx.x;
    if (i < NN)   g_cnt[i] = 0;
    if (i < ZZ)   g_scnt[i] = 0;
    if (i < NPAD) g_norder[i] = -1;
}

__global__ void hist_kernel(const int* __restrict__ receivers,
                            const int* __restrict__ species)
{
    int i = blockIdx.x * blockDim.x + threadIdx.x;
    if (i < EE) atomicAdd(&g_cnt[receivers[i]], 1);
    if (i < NN) atomicAdd(&g_scnt[species[i]], 1);
}

// ---------------- sort phase 2: scans ------------------------------------------
__global__ void scan_kernel()   // 1 block, 1024 threads; NN = 1024*32
{
    __shared__ int part[1024];
    int tid = threadIdx.x;
    int base = tid * 32;
    int loc[32];
    int sum = 0;
#pragma unroll
    for (int j = 0; j < 32; j++) { loc[j] = sum; sum += g_cnt[base + j]; }
    part[tid] = sum;
    __syncthreads();
    for (int o = 1; o < 1024; o <<= 1) {
        int v = (tid >= o) ? part[tid - o] : 0;
        __syncthreads();
        part[tid] += v;
        __syncthreads();
    }
    int pref = part[tid] - sum;   // exclusive prefix for this chunk
#pragma unroll
    for (int j = 0; j < 32; j++) {
        int o = pref + loc[j];
        g_off[base + j] = o;
        g_cur[base + j] = o;
    }
    if (tid == 1023) g_off[NN] = part[1023];
}

__global__ void species_scan_kernel()   // 1 thread, Z=10
{
    int off = 0;
    for (int z = 0; z < ZZ; z++) {
        g_scur[z] = off;
        off += ((g_scnt[z] + 63) / 64) * 64;   // pad to block multiple
    }
}

// ---------------- sort phase 3: scatter ----------------------------------------
__global__ void species_scatter_kernel(const int* __restrict__ species)
{
    int n = blockIdx.x * blockDim.x + threadIdx.x;
    if (n >= NN) return;
    int pos = atomicAdd(&g_scur[species[n]], 1);
    g_norder[pos] = n;
}

// precompute bessel + Y and scatter into receiver-sorted slots
__global__ void precompute_kernel(const float* __restrict__ vectors,
                                  const int* __restrict__ senders,
                                  const int* __restrict__ receivers)
{
    int e = blockIdx.x * blockDim.x + threadIdx.x;
    if (e >= EE) return;
    float x = vectors[e * 3 + 0];
    float y = vectors[e * 3 + 1];
    float z = vectors[e * 3 + 2];
    float r2 = x * x + y * y + z * z + 1e-12f;
    float r  = sqrtf(r2);
    float inv = 1.0f / r;
    float rc = fmaxf(r, 1e-6f);
    float r6 = r2 * r2 * r2;
    float env = 1.0f - 28.0f * r6 + 48.0f * r6 * r - 21.0f * r6 * r2;  // p=6 envelope
    if (r >= 1.0f) env = 0.0f;
    float kk = env * 1.4142135623730951f / rc;
    float pr = 3.14159265358979323846f * rc;
    float rb[NBB];
#pragma unroll
    for (int n = 1; n <= NBB; n++)
        rb[n - 1] = kk * __sinf((float)n * pr);

    int pos = atomicAdd(&g_cur[receivers[e]], 1);
    g_Y4s[pos] = make_float4(x * inv, y * inv, z * inv, 0.f);
    g_rbf4s[pos * 2 + 0] = make_float4(rb[0], rb[1], rb[2], rb[3]);
    g_rbf4s[pos * 2 + 1] = make_float4(rb[4], rb[5], rb[6], rb[7]);
    g_snds[pos] = senders[e];
}

// ---------------- node embedding init ----------------------------------------
__global__ void init_kernel(const float* __restrict__ embed_s,
                            const int* __restrict__ spec)
{
    int i = blockIdx.x * blockDim.x + threadIdx.x;  // N*F threads
    int n = i >> 6;
    int f = i & 63;
    g_s0[i] = embed_s[spec[n] * FF + f];
}

// ---------------- fused edge gather + segmented reduction (f32x2) --------------
// 32 threads own one receiver node; each thread handles an f-pair (2t, 2t+1).
template <int ITER>
__global__ void __launch_bounds__(128)
edge_agg_kernel(const float* __restrict__ Wr_i)   // [8,320] for this layer
{
    const float* s = (ITER == 0) ? g_s0 : g_s1;

    int slot = threadIdx.x >> 5;   // 4 nodes per 128-thread block
    int t    = threadIdx.x & 31;   // f-pair index
    int n    = blockIdx.x * 4 + slot;

    // register-cache packed radial weights for this thread's f-pair
    u64 wr0[NBB], wr1[NBB], wr2[NBB], wr3[NBB], wr4[NBB];
#pragma unroll
    for (int b = 0; b < NBB; b++) {
        const float* wr = Wr_i + b * 320 + 2 * t;
        wr0[b] = *(const u64*)(wr);
        wr2[b] = *(const u64*)(wr + 128);
        if (ITER > 0) {
            wr1[b] = *(const u64*)(wr + 64);
            wr3[b] = *(const u64*)(wr + 192);
            wr4[b] = *(const u64*)(wr + 256);
        }
    }

    int beg = g_off[n], end = g_off[n + 1];
    u64 as = 0ull, ax = 0ull, ay = 0ull, az = 0ull;   // packed (+0,+0)

#pragma unroll 2
    for (int i = beg; i < end; i++) {
        int snd = g_snds[i];                      // uniform -> broadcast
        float4 yv  = g_Y4s[i];
        float4 rba = g_rbf4s[i * 2 + 0];
        float4 rbb = g_rbf4s[i * 2 + 1];
        float rb[NBB] = {rba.x, rba.y, rba.z, rba.w, rbb.x, rbb.y, rbb.z, rbb.w};

        u64 w0 = 0ull, w1 = 0ull, w2 = 0ull, w3 = 0ull, w4 = 0ull;
#pragma unroll
        for (int b = 0; b < NBB; b++) {
            u64 rb2 = bcast2(rb[b]);
            w0 = fma2(rb2, wr0[b], w0);
            w2 = fma2(rb2, wr2[b], w2);
            if (ITER > 0) {
                w1 = fma2(rb2, wr1[b], w1);
                w3 = fma2(rb2, wr3[b], w3);
                w4 = fma2(rb2, wr4[b], w4);
            }
        }

        u64 ss = *(const u64*)&s[snd * FF + 2 * t];
        u64 y02 = bcast2(yv.x), y12 = bcast2(yv.y), y22 = bcast2(yv.z);

        if (ITER == 0) {
            as = fma2(w0, ss, as);
            u64 w2s = mul2(w2, ss);
            ax = fma2(w2s, y02, ax);
            ay = fma2(w2s, y12, ay);
            az = fma2(w2s, y22, az);
        } else {
            const float* vb = g_v0 + snd * 3 * FF + 2 * t;
            u64 vx = *(const u64*)(vb);
            u64 vy = *(const u64*)(vb + 64);
            u64 vz = *(const u64*)(vb + 128);
            u64 dot = fma2(vx, y02, fma2(vy, y12, mul2(vz, y22)));
            as = fma2(w0, ss, fma2(w1, dot, as));
            u64 ny02 = bcast2(-yv.x), ny12 = bcast2(-yv.y), ny22 = bcast2(-yv.z);
            u64 c0 = fma2(vy, y22, mul2(vz, ny12));
            u64 c1 = fma2(vz, y02, mul2(vx, ny22));
            u64 c2 = fma2(vx, y12, mul2(vy, ny02));
            u64 w2s = mul2(w2, ss);
            ax = fma2(w2s, y02, fma2(w3, vx, fma2(w4, c0, ax)));
            ay = fma2(w2s, y12, fma2(w3, vy, fma2(w4, c1, ay)));
            az = fma2(w2s, y22, fma2(w3, vz, fma2(w4, c2, az)));
        }
    }

    float2 fs = u2f(as), fx = u2f(ax), fy = u2f(ay), fz = u2f(az);
    g_agg[n * FF + 2 * t + 0] = make_float4(fs.x, fx.x, fy.x, fz.x);
    g_agg[n * FF + 2 * t + 1] = make_float4(fs.y, fx.y, fy.y, fz.y);
}

// ---------------- node kernel layer 0 (f32x2; 16 threads/node, 4 out/thread) ---
#define SMEM_NODE0 ((4 * 4096 + 16 * 256) * 4)   /* 80 KB */

__global__ void __launch_bounds__(256)
node0_kernel(const float* __restrict__ Wls, const float* __restrict__ Wlv,
             const float* __restrict__ Wps, const float* __restrict__ Wpv,
             const int* __restrict__ species,
             const float* __restrict__ pw,     // [Z,9,F] layer 0
             const float* __restrict__ Wread0,
             float* __restrict__ out)
{
    extern __shared__ float sm[];
    float* sWls = sm;
    float* sWlv = sm + 4096;
    float* sWps = sm + 8192;
    float* sWpv = sm + 12288;
    float* sStage = sm + 16384;            // 16 slots x 256 floats

    for (int i = threadIdx.x; i < 4096; i += 256) {
        sWls[i] = Wls[i];
        sWlv[i] = Wlv[i];
        sWps[i] = Wps[i];
        sWpv[i] = Wpv[i];
    }
    __syncthreads();

    int wid  = threadIdx.x >> 5;
    int lane = threadIdx.x & 31;
    int half = lane >> 4;                  // which node of the warp's pair
    int l4   = lane & 15;
    int go   = l4 * 4;                     // 4 outputs per thread

    float* stA = sStage + (wid * 2 + half) * 256;  // 64: agg_s / ps
    float* stV = stA + 64;                         // 192: agg_v / pv

#pragma unroll 1
    for (int chunk = 0; chunk < 4; chunk++) {
        int n = blockIdx.x * 64 + chunk * 16 + wid * 2 + half;

        // ---- stage (4x LDG.128 -> 4x STS.128) ----
        {
            float4 q0 = g_agg[n * FF + go + 0];
            float4 q1 = g_agg[n * FF + go + 1];
            float4 q2 = g_agg[n * FF + go + 2];
            float4 q3 = g_agg[n * FF + go + 3];
            *(float4*)&stA[go]       = make_float4(q0.x * EPS_SC, q1.x * EPS_SC, q2.x * EPS_SC, q3.x * EPS_SC);
            *(float4*)&stV[go]       = make_float4(q0.y * EPS_SC, q1.y * EPS_SC, q2.y * EPS_SC, q3.y * EPS_SC);
            *(float4*)&stV[64 + go]  = make_float4(q0.z * EPS_SC, q1.z * EPS_SC, q2.z * EPS_SC, q3.z * EPS_SC);
            *(float4*)&stV[128 + go] = make_float4(q0.w * EPS_SC, q1.w * EPS_SC, q2.w * EPS_SC, q3.w * EPS_SC);
        }
        __syncwarp();

        int spec = species[n];

        // ---- first matvec: 4 outputs, packed pairs (01)(23) ----
        u64 s01 = 0ull, s23 = 0ull, x01 = 0ull, x23 = 0ull;
        u64 y01 = 0ull, y23 = 0ull, z01 = 0ull, z23 = 0ull;
#pragma unroll 4
        for (int f4 = 0; f4 < FF; f4 += 4) {
            float aa[4], xx[4], yy[4], zz[4];
            *(float4*)aa = *(const float4*)&stA[f4];
            *(float4*)xx = *(const float4*)&stV[f4];
            *(float4*)yy = *(const float4*)&stV[64 + f4];
            *(float4*)zz = *(const float4*)&stV[128 + f4];
#pragma unroll
            for (int j = 0; j < 4; j++) {
                int f = f4 + j;
                u64 a2 = bcast2(aa[j]), vx2 = bcast2(xx[j]);
                u64 vy2 = bcast2(yy[j]), vz2 = bcast2(zz[j]);
                const float* wp = &sWls[f * 64 + go];
                u64 wl01 = *(const u64*)wp, wl23 = *(const u64*)(wp + 2);
                s01 = fma2(a2, wl01, s01);  s23 = fma2(a2, wl23, s23);
                wp = &sWlv[f * 64 + go];
                u64 wv01 = *(const u64*)wp, wv23 = *(const u64*)(wp + 2);
                x01 = fma2(vx2, wv01, x01); x23 = fma2(vx2, wv23, x23);
                y01 = fma2(vy2, wv01, y01); y23 = fma2(vy2, wv23, y23);
                z01 = fma2(vz2, wv01, z01); z23 = fma2(vz2, wv23, z23);
            }
        }

        // ---- product basis (scalar, 4 outputs) ----
        float sv[4], vx[4], vy[4], vz[4];
        { float2 a = u2f(s01), b = u2f(s23); sv[0]=a.x; sv[1]=a.y; sv[2]=b.x; sv[3]=b.y; }
        { float2 a = u2f(x01), b = u2f(x23); vx[0]=a.x; vx[1]=a.y; vx[2]=b.x; vx[3]=b.y; }
        { float2 a = u2f(y01), b = u2f(y23); vy[0]=a.x; vy[1]=a.y; vy[2]=b.x; vy[3]=b.y; }
        { float2 a = u2f(z01), b = u2f(z23); vz[0]=a.x; vz[1]=a.y; vz[2]=b.x; vz[3]=b.y; }

        const float* pbp = pw + spec * 9 * FF + go;
        float P[9][4];
#pragma unroll
        for (int r = 0; r < 9; r++)
            *(float4*)P[r] = *(const float4*)&pbp[r * 64];

        float ps[4], pc[4];
#pragma unroll
        for (int k = 0; k < 4; k++) {
            float vv = vx[k]*vx[k] + vy[k]*vy[k] + vz[k]*vz[k];
            float sq = sv[k]*sv[k];
            ps[k] = P[0][k]*sv[k] + P[1][k]*sq + P[2][k]*vv + P[3][k]*sq*sv[k] + P[4][k]*sv[k]*vv;
            pc[k] = P[5][k] + P[6][k]*sv[k] + P[7][k]*sq + P[8][k]*vv;
        }

        __syncwarp();
        *(float4*)&stA[go]       = make_float4(ps[0], ps[1], ps[2], ps[3]);
        *(float4*)&stV[go]       = make_float4(pc[0]*vx[0], pc[1]*vx[1], pc[2]*vx[2], pc[3]*vx[3]);
        *(float4*)&stV[64 + go]  = make_float4(pc[0]*vy[0], pc[1]*vy[1], pc[2]*vy[2], pc[3]*vy[3]);
        *(float4*)&stV[128 + go] = make_float4(pc[0]*vz[0], pc[1]*vz[1], pc[2]*vz[2], pc[3]*vz[3]);
        __syncwarp();

        // ---- second matvec ----
        u64 t01 = 0ull, t23 = 0ull, u01 = 0ull, u23 = 0ull;
        u64 v01 = 0ull, v23 = 0ull, w01a = 0ull, w23a = 0ull;
#pragma unroll 4
        for (int f4 = 0; f4 < FF; f4 += 4) {
            float aa[4], xx[4], yy[4], zz[4];
            *(float4*)aa = *(const float4*)&stA[f4];
            *(float4*)xx = *(const float4*)&stV[f4];
            *(float4*)yy = *(const float4*)&stV[64 + f4];
            *(float4*)zz = *(const float4*)&stV[128 + f4];
#pragma unroll
            for (int j = 0; j < 4; j++) {
                int f = f4 + j;
                u64 a2 = bcast2(aa[j]), vx2 = bcast2(xx[j]);
                u64 vy2 = bcast2(yy[j]), vz2 = bcast2(zz[j]);
                const float* wp = &sWps[f * 64 + go];
                u64 wl01 = *(const u64*)wp, wl23 = *(const u64*)(wp + 2);
                t01 = fma2(a2, wl01, t01);  t23 = fma2(a2, wl23, t23);
                wp = &sWpv[f * 64 + go];
                u64 wv01 = *(const u64*)wp, wv23 = *(const u64*)(wp + 2);
                u01 = fma2(vx2, wv01, u01); u23 = fma2(vx2, wv23, u23);
                v01 = fma2(vy2, wv01, v01); v23 = fma2(vy2, wv23, v23);
                w01a = fma2(vz2, wv01, w01a); w23a = fma2(vz2, wv23, w23a);
            }
        }

        float sn[4], nx[4], ny[4], nz[4];
        { float2 a = u2f(t01), b = u2f(t23); sn[0]=a.x; sn[1]=a.y; sn[2]=b.x; sn[3]=b.y; }
        { float2 a = u2f(u01), b = u2f(u23); nx[0]=a.x; nx[1]=a.y; nx[2]=b.x; nx[3]=b.y; }
        { float2 a = u2f(v01), b = u2f(v23); ny[0]=a.x; ny[1]=a.y; ny[2]=b.x; ny[3]=b.y; }
        { float2 a = u2f(w01a), b = u2f(w23a); nz[0]=a.x; nz[1]=a.y; nz[2]=b.x; nz[3]=b.y; }

        *(float4*)&g_s1[n * FF + go] = make_float4(sn[0], sn[1], sn[2], sn[3]);
        float* vo = g_v0 + n * 3 * FF;
        *(float4*)&vo[go]       = make_float4(nx[0], nx[1], nx[2], nx[3]);
        *(float4*)&vo[64 + go]  = make_float4(ny[0], ny[1], ny[2], ny[3]);
        *(float4*)&vo[128 + go] = make_float4(nz[0], nz[1], nz[2], nz[3]);

        // ---- linear readout: 16-lane reduce ----
        float4 wr = *(const float4*)&Wread0[go];
        float t = sn[0]*wr.x + sn[1]*wr.y + sn[2]*wr.z + sn[3]*wr.w;
#pragma unroll
        for (int o = 8; o > 0; o >>= 1)
            t += __shfl_xor_sync(0xffffffffu, t, o);
        if (l4 == 0) out[n * LL + 0] = t;
        __syncwarp();
    }
}

// ---------------- node kernel layer 1 (species-grouped; f32x2) ------------------
#define SMEM_NODE1 ((6 * 4096 + 16 * 512) * 4)   /* 128 KB */

__global__ void __launch_bounds__(256)
node1_kernel(const float* __restrict__ Wls, const float* __restrict__ Wlv,
             const float* __restrict__ Wps,
             const int* __restrict__ species,
             const float* __restrict__ skip_s, const float* __restrict__ skip_v,
             const float* __restrict__ pw,     // [Z,9,F] layer 1
             const float* __restrict__ Wr1a, const float* __restrict__ Wr1b,
             float* __restrict__ out)
{
    int n0 = g_norder[blockIdx.x * 64];
    if (n0 < 0) return;                    // fully-padded block
    int spec = species[n0];                // uniform for the whole block

    extern __shared__ float sm[];
    float* sWls = sm;
    float* sWlv = sm + 4096;
    float* sWps = sm + 8192;
    float* sKs  = sm + 12288;
    float* sKv  = sm + 16384;
    float* sStage = sm + 24576 - 4096;     // 20480: 16 slots x 512 floats

    {
        const float* ks = skip_s + spec * 4096;
        const float* kv = skip_v + spec * 4096;
        for (int i = threadIdx.x; i < 4096; i += 256) {
            sWls[i] = Wls[i];
            sWlv[i] = Wlv[i];
            sWps[i] = Wps[i];
            sKs[i]  = ks[i];
            sKv[i]  = kv[i];
        }
    }
    __syncthreads();

    int wid  = threadIdx.x >> 5;
    int lane = threadIdx.x & 31;
    int half = lane >> 4;
    int l4   = lane & 15;
    int go   = l4 * 4;

    float* stA  = sStage + (wid * 2 + half) * 512;  // 64:  agg_s / ps
    float* stV  = stA + 64;                         // 192: agg_v / pv
    float* stS  = stA + 256;                        // 64:  old s
    float* stVi = stA + 320;                        // 192: old v

    const float* pbp = pw + spec * 9 * FF + go;
    float P[9][4];
#pragma unroll
    for (int r = 0; r < 9; r++)
        *(float4*)P[r] = *(const float4*)&pbp[r * 64];

#pragma unroll 1
    for (int chunk = 0; chunk < 4; chunk++) {
        int idx = blockIdx.x * 64 + chunk * 16 + wid * 2 + half;
        int nn = g_norder[idx];
        bool valid = (nn >= 0);
        int n = valid ? nn : n0;

        // ---- stage ----
        {
            float4 q0 = g_agg[n * FF + go + 0];
            float4 q1 = g_agg[n * FF + go + 1];
            float4 q2 = g_agg[n * FF + go + 2];
            float4 q3 = g_agg[n * FF + go + 3];
            *(float4*)&stA[go]       = make_float4(q0.x * EPS_SC, q1.x * EPS_SC, q2.x * EPS_SC, q3.x * EPS_SC);
            *(float4*)&stV[go]       = make_float4(q0.y * EPS_SC, q1.y * EPS_SC, q2.y * EPS_SC, q3.y * EPS_SC);
            *(float4*)&stV[64 + go]  = make_float4(q0.z * EPS_SC, q1.z * EPS_SC, q2.z * EPS_SC, q3.z * EPS_SC);
            *(float4*)&stV[128 + go] = make_float4(q0.w * EPS_SC, q1.w * EPS_SC, q2.w * EPS_SC, q3.w * EPS_SC);
            *(float4*)&stS[go] = *(const float4*)&g_s1[n * FF + go];
            const float* vb = g_v0 + n * 3 * FF;
            *(float4*)&stVi[go]       = *(const float4*)&vb[go];
            *(float4*)&stVi[64 + go]  = *(const float4*)&vb[64 + go];
            *(float4*)&stVi[128 + go] = *(const float4*)&vb[128 + go];
        }
        __syncwarp();

        // ---- first matvec + skip matvecs ----
        u64 s01 = 0ull, s23 = 0ull, x01 = 0ull, x23 = 0ull;
        u64 y01 = 0ull, y23 = 0ull, z01 = 0ull, z23 = 0ull;
        u64 c01 = 0ull, c23 = 0ull, d01 = 0ull, d23 = 0ull;
        u64 e01 = 0ull, e23 = 0ull, h01 = 0ull, h23 = 0ull;
#pragma unroll 4
        for (int f4 = 0; f4 < FF; f4 += 4) {
            float aa[4], xx[4], yy[4], zz[4], si[4], ux[4], uy[4], uz[4];
            *(float4*)aa = *(const float4*)&stA[f4];
            *(float4*)xx = *(const float4*)&stV[f4];
            *(float4*)yy = *(const float4*)&stV[64 + f4];
            *(float4*)zz = *(const float4*)&stV[128 + f4];
            *(float4*)si = *(const float4*)&stS[f4];
            *(float4*)ux = *(const float4*)&stVi[f4];
            *(float4*)uy = *(const float4*)&stVi[64 + f4];
            *(float4*)uz = *(const float4*)&stVi[128 + f4];
#pragma unroll
            for (int j = 0; j < 4; j++) {
                int f = f4 + j;
                u64 a2 = bcast2(aa[j]), vx2 = bcast2(xx[j]);
                u64 vy2 = bcast2(yy[j]), vz2 = bcast2(zz[j]);
                const float* wp = &sWls[f * 64 + go];
                u64 w0 = *(const u64*)wp, w1 = *(const u64*)(wp + 2);
                s01 = fma2(a2, w0, s01);  s23 = fma2(a2, w1, s23);
                wp = &sWlv[f * 64 + go];
                w0 = *(const u64*)wp; w1 = *(const u64*)(wp + 2);
                x01 = fma2(vx2, w0, x01); x23 = fma2(vx2, w1, x23);
                y01 = fma2(vy2, w0, y01); y23 = fma2(vy2, w1, y23);
                z01 = fma2(vz2, w0, z01); z23 = fma2(vz2, w1, z23);

                u64 s2 = bcast2(si[j]), ux2 = bcast2(ux[j]);
                u64 uy2 = bcast2(uy[j]), uz2 = bcast2(uz[j]);
                wp = &sKs[f * 64 + go];
                w0 = *(const u64*)wp; w1 = *(const u64*)(wp + 2);
                c01 = fma2(s2, w0, c01);  c23 = fma2(s2, w1, c23);
                wp = &sKv[f * 64 + go];
                w0 = *(const u64*)wp; w1 = *(const u64*)(wp + 2);
                d01 = fma2(ux2, w0, d01); d23 = fma2(ux2, w1, d23);
                e01 = fma2(uy2, w0, e01); e23 = fma2(uy2, w1, e23);
                h01 = fma2(uz2, w0, h01); h23 = fma2(uz2, w1, h23);
            }
        }
        // NOTE: skip-v result (d,e,h) is dead — layer-1 v output is never read.
        (void)d01; (void)d23; (void)e01; (void)e23; (void)h01; (void)h23;

        // ---- product basis ----
        float sv[4], vx[4], vy[4], vz[4], sc[4];
        { float2 a = u2f(s01), b = u2f(s23); sv[0]=a.x; sv[1]=a.y; sv[2]=b.x; sv[3]=b.y; }
        { float2 a = u2f(x01), b = u2f(x23); vx[0]=a.x; vx[1]=a.y; vx[2]=b.x; vx[3]=b.y; }
        { float2 a = u2f(y01), b = u2f(y23); vy[0]=a.x; vy[1]=a.y; vy[2]=b.x; vy[3]=b.y; }
        { float2 a = u2f(z01), b = u2f(z23); vz[0]=a.x; vz[1]=a.y; vz[2]=b.x; vz[3]=b.y; }
        { float2 a = u2f(c01), b = u2f(c23); sc[0]=a.x; sc[1]=a.y; sc[2]=b.x; sc[3]=b.y; }

        float ps[4];
#pragma unroll
        for (int k = 0; k < 4; k++) {
            float vv = vx[k]*vx[k] + vy[k]*vy[k] + vz[k]*vz[k];
            float sq = sv[k]*sv[k];
            ps[k] = P[0][k]*sv[k] + P[1][k]*sq + P[2][k]*vv + P[3][k]*sq*sv[k] + P[4][k]*sv[k]*vv;
        }

        __syncwarp();
        *(float4*)&stA[go] = make_float4(ps[0], ps[1], ps[2], ps[3]);
        __syncwarp();

        // ---- second matvec: s channel only (+ skip), then nonlinear readout ----
        u64 t01 = pack2(sc[0], sc[1]), t23 = pack2(sc[2], sc[3]);
#pragma unroll 4
        for (int f4 = 0; f4 < FF; f4 += 4) {
            float aa[4];
            *(float4*)aa = *(const float4*)&stA[f4];
#pragma unroll
            for (int j = 0; j < 4; j++) {
                int f = f4 + j;
                u64 a2 = bcast2(aa[j]);
                const float* wp = &sWps[f * 64 + go];
                t01 = fma2(a2, *(const u64*)wp, t01);
                t23 = fma2(a2, *(const u64*)(wp + 2), t23);
            }
        }
        float sn[4];
        { float2 a = u2f(t01), b = u2f(t23); sn[0]=a.x; sn[1]=a.y; sn[2]=b.x; sn[3]=b.y; }

        __syncwarp();
        *(float4*)&stA[go] = make_float4(sn[0], sn[1], sn[2], sn[3]);
        __syncwarp();

        // hidden layer: all 16 lanes of each node compute one hidden unit
        float h = 0.f;
#pragma unroll
        for (int f4 = 0; f4 < FF; f4 += 4) {
            float aa[4];
            *(float4*)aa = *(const float4*)&stA[f4];
#pragma unroll
            for (int j = 0; j < 4; j++)
                h = fmaf(aa[j], Wr1a[(f4 + j) * HH + l4], h);
        }
        h = h / (1.0f + expf(-h));  // silu
        float t = h * Wr1b[l4];
#pragma unroll
        for (int o = 8; o > 0; o >>= 1)
            t += __shfl_xor_sync(0xffffffffu, t, o);
        if (l4 == 0 && valid) out[n * LL + 1] = t;
        __syncwarp();
    }
}

// ---------------- host launch -------------------------------------------------
extern "C" void kernel_launch(void* const* d_in, const int* in_sizes, int n_in,
                              void* d_out, int out_size)
{
    const float* vectors  = (const float*)d_in[0];
    const float* embed_s  = (const float*)d_in[1];
    const float* Wr       = (const float*)d_in[2];   // [2,8,320]
    const float* Wls      = (const float*)d_in[3];   // [2,64,64]
    const float* Wlv      = (const float*)d_in[4];
    const float* skip_s   = (const float*)d_in[5];   // [10,64,64]
    const float* skip_v   = (const float*)d_in[6];
    const float* pw       = (const float*)d_in[7];   // [2,10,9,64]
    const float* Wps      = (const float*)d_in[8];
    const float* Wpv      = (const float*)d_in[9];
    const float* Wread0   = (const float*)d_in[10];  // [64,1]
    const float* Wr1a     = (const float*)d_in[11];  // [64,16]
    const float* Wr1b     = (const float*)d_in[12];  // [16,1]
    const int*   senders  = (const int*)d_in[13];
    const int*   receivers= (const int*)d_in[14];
    const int*   species  = (const int*)d_in[15];
    float* out = (float*)d_out;

    static bool attr_done = false;
    if (!attr_done) {
        cudaFuncSetAttribute((const void*)node0_kernel,
                             cudaFuncAttributeMaxDynamicSharedMemorySize, SMEM_NODE0);
        cudaFuncSetAttribute((const void*)node1_kernel,
                             cudaFuncAttributeMaxDynamicSharedMemorySize, SMEM_NODE1);
        attr_done = true;
    }

    // ---- CSR sorts (receiver CSR + species grouping) ----
    zero_sort_kernel<<<(NPAD + 255) / 256, 256>>>();
    hist_kernel<<<EE / 256, 256>>>(receivers, species);
    scan_kernel<<<1, 1024>>>();
    species_scan_kernel<<<1, 1>>>();
    precompute_kernel<<<EE / 256, 256>>>(vectors, senders, receivers);
    species_scatter_kernel<<<NN / 256, 256>>>(species);
    init_kernel<<<(NN * FF) / 256, 256>>>(embed_s, species);

    // ---- layer 0 ----
    edge_agg_kernel<0><<<NN / 4, 128>>>(Wr);
    node0_kernel<<<NN / 64, 256, SMEM_NODE0>>>(
        Wls, Wlv, Wps, Wpv, species, pw, Wread0, out);

    // ---- layer 1 ----
    edge_agg_kernel<1><<<NN / 4, 128>>>(Wr + NBB * 5 * FF);
    node1_kernel<<<NPAD / 64, 256, SMEM_NODE1>>>(
        Wls + FF * FF, Wlv + FF * FF, Wps + FF * FF,
        species, skip_s, skip_v, pw + ZZ * 9 * FF,
        Wr1a, Wr1b, out);
}

// round 10
// speedup vs baseline: 1.3067x; 1.1123x over previous
#include <cuda_runtime.h>
#include <cuda_bf16.h>
#include <math.h>

#define NN 32768
#define EE 262144
#define FF 64
#define ZZ 10
#define NBB 8
#define LL 2
#define HH 16
#define NPAD (NN + 64 * ZZ)              /* species-padded node ordering */
#define EPS_SC 0.24253562503633297f      /* 1/sqrt(17) */

typedef unsigned long long u64;

// ---------------- packed fp32x2 helpers ----------------------------------------
__device__ __forceinline__ u64 pack2(float lo, float hi) {
    u64 r; asm("mov.b64 %0, {%1, %2};" : "=l"(r) : "f"(lo), "f"(hi)); return r;
}
__device__ __forceinline__ u64 bcast2(float v) { return pack2(v, v); }
__device__ __forceinline__ float2 u2f(u64 v) {
    float2 r; asm("mov.b64 {%0, %1}, %2;" : "=f"(r.x), "=f"(r.y) : "l"(v)); return r;
}
__device__ __forceinline__ u64 fma2(u64 a, u64 b, u64 c) {
    u64 r; asm("fma.rn.f32x2 %0, %1, %2, %3;" : "=l"(r) : "l"(a), "l"(b), "l"(c)); return r;
}
__device__ __forceinline__ u64 mul2(u64 a, u64 b) {
    u64 r; asm("mul.rn.f32x2 %0, %1, %2;" : "=l"(r) : "l"(a), "l"(b)); return r;
}

// ---------------- scratch (static device globals; no allocation) -------------
__device__ float  g_s0[NN * FF];
__device__ float  g_s1[NN * FF];
__device__ float  g_v0[NN * 3 * FF];     // [n][k][f]
__device__ float4 g_rbf4s[EE * 2];       // bessel basis, receiver-sorted
__device__ float4 g_Y4s[EE];             // unit vector, receiver-sorted
__device__ int    g_snds[EE];            // senders, receiver-sorted
__device__ int    g_cnt[NN];             // receiver histogram
__device__ int    g_cur[NN];             // scatter cursors
__device__ int    g_off[NN + 1];         // CSR offsets
__device__ int    g_scnt[ZZ];            // species histogram
__device__ int    g_scur[ZZ];
__device__ int    g_norder[NPAD];        // species-grouped node order (-1 pad)

// ---------------- preprocessing ------------------------------------------------
__global__ void zero_sort_kernel()
{
    int i = blockIdx.x * blockDim.x + threadIdx.x;
    if (i < NN)   g_cnt[i] = 0;
    if (i < ZZ)   g_scnt[i] = 0;
    if (i < NPAD) g_norder[i] = -1;
}

__global__ void hist_kernel(const int* __restrict__ receivers,
                            const int* __restrict__ species)
{
    int i = blockIdx.x * blockDim.x + threadIdx.x;
    if (i < EE) atomicAdd(&g_cnt[receivers[i]], 1);
    if (i < NN) atomicAdd(&g_scnt[species[i]], 1);
}

__global__ void scan_kernel()   // 1 block, 1024 threads; NN = 1024*32
{
    __shared__ int part[1024];
    int tid = threadIdx.x;

    if (tid == 0) {             // tiny species scan folded in
        int off = 0;
#pragma unroll
        for (int z = 0; z < ZZ; z++) {
            g_scur[z] = off;
            off += ((g_scnt[z] + 63) / 64) * 64;
        }
    }

    int base = tid * 32;
    int loc[32];
    int sum = 0;
#pragma unroll
    for (int j = 0; j < 32; j++) { loc[j] = sum; sum += g_cnt[base + j]; }
    part[tid] = sum;
    __syncthreads();
    for (int o = 1; o < 1024; o <<= 1) {
        int v = (tid >= o) ? part[tid - o] : 0;
        __syncthreads();
        part[tid] += v;
        __syncthreads();
    }
    int pref = part[tid] - sum;
#pragma unroll
    for (int j = 0; j < 32; j++) {
        int o = pref + loc[j];
        g_off[base + j] = o;
        g_cur[base + j] = o;
    }
    if (tid == 1023) g_off[NN] = part[1023];
}

// precompute (edge scatter) + species scatter + embedding init, one launch
__global__ void fused_pre_kernel(const float* __restrict__ vectors,
                                 const float* __restrict__ embed_s,
                                 const int* __restrict__ senders,
                                 const int* __restrict__ receivers,
                                 const int* __restrict__ species)
{
    int idx = blockIdx.x * blockDim.x + threadIdx.x;   // NN*FF threads

    if (idx < NN * FF) {
        int n = idx >> 6, f = idx & 63;
        g_s0[idx] = embed_s[species[n] * FF + f];
    }

    if (idx < EE) {
        float x = vectors[idx * 3 + 0];
        float y = vectors[idx * 3 + 1];
        float z = vectors[idx * 3 + 2];
        float r2 = x * x + y * y + z * z + 1e-12f;
        float r  = sqrtf(r2);
        float inv = 1.0f / r;
        float rc = fmaxf(r, 1e-6f);
        float r6 = r2 * r2 * r2;
        float env = 1.0f - 28.0f * r6 + 48.0f * r6 * r - 21.0f * r6 * r2;
        if (r >= 1.0f) env = 0.0f;
        float kk = env * 1.4142135623730951f / rc;
        float pr = 3.14159265358979323846f * rc;
        float rb[NBB];
#pragma unroll
        for (int n2 = 1; n2 <= NBB; n2++)
            rb[n2 - 1] = kk * __sinf((float)n2 * pr);

        int pos = atomicAdd(&g_cur[receivers[idx]], 1);
        g_Y4s[pos] = make_float4(x * inv, y * inv, z * inv, 0.f);
        g_rbf4s[pos * 2 + 0] = make_float4(rb[0], rb[1], rb[2], rb[3]);
        g_rbf4s[pos * 2 + 1] = make_float4(rb[4], rb[5], rb[6], rb[7]);
        g_snds[pos] = senders[idx];
    }

    if (idx < NN) {
        int pos = atomicAdd(&g_scur[species[idx]], 1);
        g_norder[pos] = idx;
    }
}

// ---------------- fused per-layer kernel ---------------------------------------
// One warp per node: CSR edge reduce (f32x2, f-pairs) -> shared stage ->
// matvecs + product basis + skip + readout (2 outputs/thread).
#define SMEM_L0 ((16384 + 2560 + 8 * 256) * 4)   /*  84 KB */
#define SMEM_L1 ((20480 + 2560 + 8 * 512) * 4)   /* 108 KB */

template <int ITER>
__global__ void __launch_bounds__(256, 2)
layer_kernel(const float* __restrict__ Wr_i,     // [8,320] this layer
             const float* __restrict__ Wls, const float* __restrict__ Wlv,
             const float* __restrict__ Wps,
             const float* __restrict__ Wpv,      // ITER0 only
             const float* __restrict__ skip_s,   // ITER1 only
             const float* __restrict__ skip_v,   // ITER1 only
             const int* __restrict__ species,
             const float* __restrict__ pw_i,     // [Z,9,F] this layer
             const float* __restrict__ Wread0,   // ITER0 only
             const float* __restrict__ Wr1a, const float* __restrict__ Wr1b,
             float* __restrict__ out)
{
    int spec_blk = 0;
    if (ITER == 1) {
        int n0 = g_norder[blockIdx.x * 64];
        if (n0 < 0) return;                 // fully-padded block
        spec_blk = species[n0];             // uniform for the whole block
    }

    extern __shared__ float sm[];
    float* sWls = sm;                       // 4096
    float* sWlv = sm + 4096;                // 4096
    float* sWps = sm + 8192;                // 4096
    float* sW4  = sm + 12288;               // 4096: ITER0 Wpv / ITER1 skip_s
    float* sW5  = sm + 16384;               // ITER1 only: skip_v (4096)
    float* sWr  = (ITER == 0) ? (sm + 16384) : (sm + 20480);  // 2560
    float* sStageBase = sWr + 2560;
    const int STG = (ITER == 0) ? 256 : 512;

    for (int i = threadIdx.x; i < 4096; i += 256) {
        sWls[i] = Wls[i];
        sWlv[i] = Wlv[i];
        sWps[i] = Wps[i];
        sW4[i]  = (ITER == 0) ? Wpv[i] : skip_s[spec_blk * 4096 + i];
        if (ITER == 1) sW5[i] = skip_v[spec_blk * 4096 + i];
    }
    for (int i = threadIdx.x; i < 5 * NBB * 64; i += 256) {
        int p = i >> 9, b = (i >> 6) & 7, f = i & 63;
        sWr[i] = Wr_i[b * 320 + p * 64 + f];
    }
    __syncthreads();

    int wid  = threadIdx.x >> 5;
    int t    = threadIdx.x & 31;       // f-pair (edge phase) / thread id in warp
    int go   = 2 * t;                  // output pair (node phase)

    float* stA  = sStageBase + wid * STG;  // 64:  agg_s / ps / staged sn
    float* stV  = stA + 64;                // 192: agg_v / pv
    float* stS  = stA + 256;               // 64:  old s (ITER1)
    float* stVi = stA + 320;               // 192: old v (ITER1)

    const float* sIn = (ITER == 0) ? g_s0 : g_s1;

    // per-block product-basis weights (ITER1: species uniform)
    float P1[9][2];
    if (ITER == 1) {
        const float* pbp = pw_i + spec_blk * 9 * FF + go;
#pragma unroll
        for (int r = 0; r < 9; r++) {
            float2 tmp = *(const float2*)&pbp[r * 64];
            P1[r][0] = tmp.x; P1[r][1] = tmp.y;
        }
    }

#pragma unroll 1
    for (int chunk = 0; chunk < 8; chunk++) {
        int n;
        if (ITER == 0) {
            n = blockIdx.x * 64 + chunk * 8 + wid;
        } else {
            n = g_norder[blockIdx.x * 64 + chunk * 8 + wid];
            if (n < 0) continue;           // warp-uniform
        }

        // ---- radial weights -> registers (live only through edge phase) ----
        u64 wr0[NBB], wr1[NBB], wr2[NBB], wr3[NBB], wr4[NBB];
#pragma unroll
        for (int b = 0; b < NBB; b++) {
            wr0[b] = *(const u64*)&sWr[(0 * 8 + b) * 64 + go];
            wr2[b] = *(const u64*)&sWr[(2 * 8 + b) * 64 + go];
            if (ITER > 0) {
                wr1[b] = *(const u64*)&sWr[(1 * 8 + b) * 64 + go];
                wr3[b] = *(const u64*)&sWr[(3 * 8 + b) * 64 + go];
                wr4[b] = *(const u64*)&sWr[(4 * 8 + b) * 64 + go];
            }
        }

        // ---- edge phase: walk CSR segment, accumulate in regs ----
        int beg = g_off[n], end = g_off[n + 1];
        u64 as = 0ull, ax = 0ull, ay = 0ull, az = 0ull;

#pragma unroll 2
        for (int i = beg; i < end; i++) {
            int snd = g_snds[i];                 // uniform -> broadcast
            float4 yv  = g_Y4s[i];
            float4 rba = g_rbf4s[i * 2 + 0];
            float4 rbb = g_rbf4s[i * 2 + 1];
            float rb[NBB] = {rba.x, rba.y, rba.z, rba.w, rbb.x, rbb.y, rbb.z, rbb.w};

            u64 w0 = 0ull, w1 = 0ull, w2 = 0ull, w3 = 0ull, w4 = 0ull;
#pragma unroll
            for (int b = 0; b < NBB; b++) {
                u64 rb2 = bcast2(rb[b]);
                w0 = fma2(rb2, wr0[b], w0);
                w2 = fma2(rb2, wr2[b], w2);
                if (ITER > 0) {
                    w1 = fma2(rb2, wr1[b], w1);
                    w3 = fma2(rb2, wr3[b], w3);
                    w4 = fma2(rb2, wr4[b], w4);
                }
            }

            u64 ss = *(const u64*)&sIn[snd * FF + go];
            u64 y02 = bcast2(yv.x), y12 = bcast2(yv.y), y22 = bcast2(yv.z);

            if (ITER == 0) {
                as = fma2(w0, ss, as);
                u64 w2s = mul2(w2, ss);
                ax = fma2(w2s, y02, ax);
                ay = fma2(w2s, y12, ay);
                az = fma2(w2s, y22, az);
            } else {
                const float* vb = g_v0 + snd * 3 * FF + go;
                u64 vx = *(const u64*)(vb);
                u64 vy = *(const u64*)(vb + 64);
                u64 vz = *(const u64*)(vb + 128);
                u64 dot = fma2(vx, y02, fma2(vy, y12, mul2(vz, y22)));
                as = fma2(w0, ss, fma2(w1, dot, as));
                u64 ny02 = bcast2(-yv.x), ny12 = bcast2(-yv.y), ny22 = bcast2(-yv.z);
                u64 c0 = fma2(vy, y22, mul2(vz, ny12));
                u64 c1 = fma2(vz, y02, mul2(vx, ny22));
                u64 c2 = fma2(vx, y12, mul2(vy, ny02));
                u64 w2s = mul2(w2, ss);
                ax = fma2(w2s, y02, fma2(w3, vx, fma2(w4, c0, ax)));
                ay = fma2(w2s, y12, fma2(w3, vy, fma2(w4, c1, ay)));
                az = fma2(w2s, y22, fma2(w3, vz, fma2(w4, c2, az)));
            }
        }

        // ---- stage edge results (+EPS) and skip inputs ----
        {
            float2 fs = u2f(as), fx = u2f(ax), fy = u2f(ay), fz = u2f(az);
            *(float2*)&stA[go]       = make_float2(fs.x * EPS_SC, fs.y * EPS_SC);
            *(float2*)&stV[go]       = make_float2(fx.x * EPS_SC, fx.y * EPS_SC);
            *(float2*)&stV[64 + go]  = make_float2(fy.x * EPS_SC, fy.y * EPS_SC);
            *(float2*)&stV[128 + go] = make_float2(fz.x * EPS_SC, fz.y * EPS_SC);
        }
        if (ITER > 0) {
            *(float2*)&stS[go] = *(const float2*)&g_s1[n * FF + go];
            const float* vb = g_v0 + n * 3 * FF;
            *(float2*)&stVi[go]       = *(const float2*)&vb[go];
            *(float2*)&stVi[64 + go]  = *(const float2*)&vb[64 + go];
            *(float2*)&stVi[128 + go] = *(const float2*)&vb[128 + go];
        }
        __syncwarp();

        // ---- matvec 1 (+ skip_s for ITER1; skip_v is dead -> not computed) ----
        u64 mS = 0ull, mX = 0ull, mY = 0ull, mZ = 0ull, kS = 0ull;
#pragma unroll 4
        for (int f4 = 0; f4 < FF; f4 += 4) {
            float aa[4], xx[4], yy[4], zz[4], si[4];
            *(float4*)aa = *(const float4*)&stA[f4];
            *(float4*)xx = *(const float4*)&stV[f4];
            *(float4*)yy = *(const float4*)&stV[64 + f4];
            *(float4*)zz = *(const float4*)&stV[128 + f4];
            if (ITER > 0) *(float4*)si = *(const float4*)&stS[f4];
#pragma unroll
            for (int j = 0; j < 4; j++) {
                int f = f4 + j;
                mS = fma2(bcast2(aa[j]), *(const u64*)&sWls[f * 64 + go], mS);
                u64 wv = *(const u64*)&sWlv[f * 64 + go];
                mX = fma2(bcast2(xx[j]), wv, mX);
                mY = fma2(bcast2(yy[j]), wv, mY);
                mZ = fma2(bcast2(zz[j]), wv, mZ);
                if (ITER > 0)
                    kS = fma2(bcast2(si[j]), *(const u64*)&sW4[f * 64 + go], kS);
            }
        }

        // ---- product basis (2 outputs) ----
        float2 svp = u2f(mS), vxp = u2f(mX), vyp = u2f(mY), vzp = u2f(mZ);
        float svv[2] = {svp.x, svp.y};
        float vvx[2] = {vxp.x, vxp.y};
        float vvy[2] = {vyp.x, vyp.y};
        float vvz[2] = {vzp.x, vzp.y};

        float q[9][2];
        if (ITER == 0) {
            const float* pbp = pw_i + species[n] * 9 * FF + go;
#pragma unroll
            for (int r = 0; r < 9; r++) {
                float2 tmp = *(const float2*)&pbp[r * 64];
                q[r][0] = tmp.x; q[r][1] = tmp.y;
            }
        } else {
#pragma unroll
            for (int r = 0; r < 9; r++) { q[r][0] = P1[r][0]; q[r][1] = P1[r][1]; }
        }

        float ps[2], pc[2];
#pragma unroll
        for (int k = 0; k < 2; k++) {
            float vv = vvx[k]*vvx[k] + vvy[k]*vvy[k] + vvz[k]*vvz[k];
            float sq = svv[k]*svv[k];
            ps[k] = q[0][k]*svv[k] + q[1][k]*sq + q[2][k]*vv + q[3][k]*sq*svv[k] + q[4][k]*svv[k]*vv;
            pc[k] = q[5][k] + q[6][k]*svv[k] + q[7][k]*sq + q[8][k]*vv;
        }

        __syncwarp();
        *(float2*)&stA[go] = make_float2(ps[0], ps[1]);
        if (ITER == 0) {
            *(float2*)&stV[go]       = make_float2(pc[0]*vvx[0], pc[1]*vvx[1]);
            *(float2*)&stV[64 + go]  = make_float2(pc[0]*vvy[0], pc[1]*vvy[1]);
            *(float2*)&stV[128 + go] = make_float2(pc[0]*vvz[0], pc[1]*vvz[1]);
        }
        __syncwarp();

        // ---- matvec 2 (+ skip add) ----
        u64 tS = (ITER > 0) ? kS : 0ull;
        u64 tX = 0ull, tY = 0ull, tZ = 0ull;
#pragma unroll 4
        for (int f4 = 0; f4 < FF; f4 += 4) {
            float aa[4], xx[4], yy[4], zz[4];
            *(float4*)aa = *(const float4*)&stA[f4];
            if (ITER == 0) {
                *(float4*)xx = *(const float4*)&stV[f4];
                *(float4*)yy = *(const float4*)&stV[64 + f4];
                *(float4*)zz = *(const float4*)&stV[128 + f4];
            }
#pragma unroll
            for (int j = 0; j < 4; j++) {
                int f = f4 + j;
                tS = fma2(bcast2(aa[j]), *(const u64*)&sWps[f * 64 + go], tS);
                if (ITER == 0) {
                    u64 wv = *(const u64*)&sW4[f * 64 + go];   // Wpv
                    tX = fma2(bcast2(xx[j]), wv, tX);
                    tY = fma2(bcast2(yy[j]), wv, tY);
                    tZ = fma2(bcast2(zz[j]), wv, tZ);
                }
            }
        }

        float2 snp = u2f(tS);
        if (ITER == 0) {
            // outputs feed layer 1
            *(float2*)&g_s1[n * FF + go] = snp;
            float2 nxp = u2f(tX), nyp = u2f(tY), nzp = u2f(tZ);
            float* vo = g_v0 + n * 3 * FF;
            *(float2*)&vo[go]       = nxp;
            *(float2*)&vo[64 + go]  = nyp;
            *(float2*)&vo[128 + go] = nzp;

            // linear readout
            float2 wr = *(const float2*)&Wread0[go];
            float tt = snp.x * wr.x + snp.y * wr.y;
#pragma unroll
            for (int o = 16; o > 0; o >>= 1)
                tt += __shfl_xor_sync(0xffffffffu, tt, o);
            if (t == 0) out[n * LL + 0] = tt;
        } else {
            // nonlinear readout
            __syncwarp();
            *(float2*)&stA[go] = snp;
            __syncwarp();
            float tt = 0.f;
            if (t < HH) {
                float h = 0.f;
#pragma unroll
                for (int f4 = 0; f4 < FF; f4 += 4) {
                    float aa[4];
                    *(float4*)aa = *(const float4*)&stA[f4];
#pragma unroll
                    for (int j = 0; j < 4; j++)
                        h = fmaf(aa[j], Wr1a[(f4 + j) * HH + t], h);
                }
                h = h / (1.0f + expf(-h));  // silu
                tt = h * Wr1b[t];
            }
#pragma unroll
            for (int o = 16; o > 0; o >>= 1)
                tt += __shfl_xor_sync(0xffffffffu, tt, o);
            if (t == 0) out[n * LL + 1] = tt;
        }
        __syncwarp();
    }
}

// ---------------- host launch -------------------------------------------------
extern "C" void kernel_launch(void* const* d_in, const int* in_sizes, int n_in,
                              void* d_out, int out_size)
{
    const float* vectors  = (const float*)d_in[0];
    const float* embed_s  = (const float*)d_in[1];
    const float* Wr       = (const float*)d_in[2];   // [2,8,320]
    const float* Wls      = (const float*)d_in[3];   // [2,64,64]
    const float* Wlv      = (const float*)d_in[4];
    const float* skip_s   = (const float*)d_in[5];   // [10,64,64]
    const float* skip_v   = (const float*)d_in[6];
    const float* pw       = (const float*)d_in[7];   // [2,10,9,64]
    const float* Wps      = (const float*)d_in[8];
    const float* Wpv      = (const float*)d_in[9];
    const float* Wread0   = (const float*)d_in[10];  // [64,1]
    const float* Wr1a     = (const float*)d_in[11];  // [64,16]
    const float* Wr1b     = (const float*)d_in[12];  // [16,1]
    const int*   senders  = (const int*)d_in[13];
    const int*   receivers= (const int*)d_in[14];
    const int*   species  = (const int*)d_in[15];
    float* out = (float*)d_out;

    static bool attr_done = false;
    if (!attr_done) {
        cudaFuncSetAttribute((const void*)layer_kernel<0>,
                             cudaFuncAttributeMaxDynamicSharedMemorySize, SMEM_L0);
        cudaFuncSetAttribute((const void*)layer_kernel<1>,
                             cudaFuncAttributeMaxDynamicSharedMemorySize, SMEM_L1);
        attr_done = true;
    }

    // ---- preprocessing: 4 launches ----
    zero_sort_kernel<<<(NPAD + 255) / 256, 256>>>();
    hist_kernel<<<EE / 256, 256>>>(receivers, species);
    scan_kernel<<<1, 1024>>>();
    fused_pre_kernel<<<(NN * FF) / 256, 256>>>(vectors, embed_s, senders,
                                               receivers, species);

    // ---- layer 0 (fused edge reduce + node update + linear readout) ----
    layer_kernel<0><<<NN / 64, 256, SMEM_L0>>>(
        Wr, Wls, Wlv, Wps, Wpv, nullptr, nullptr,
        species, pw, Wread0, nullptr, nullptr, out);

    // ---- layer 1 (species-grouped; fused; nonlinear readout) ----
    layer_kernel<1><<<NPAD / 64, 256, SMEM_L1>>>(
        Wr + NBB * 5 * FF, Wls + FF * FF, Wlv + FF * FF, Wps + FF * FF,
        nullptr, skip_s, skip_v,
        species, pw + ZZ * 9 * FF, nullptr, Wr1a, Wr1b, out);
}

// round 11
// speedup vs baseline: 1.3387x; 1.0245x over previous
#include <cuda_runtime.h>
#include <cuda_bf16.h>
#include <math.h>

#define NN 32768
#define EE 262144
#define FF 64
#define ZZ 10
#define NBB 8
#define LL 2
#define HH 16
#define NPAD (NN + 64 * ZZ)              /* species-padded node ordering */
#define EPS_SC 0.24253562503633297f      /* 1/sqrt(17) */

typedef unsigned long long u64;

// ---------------- packed fp32x2 helpers ----------------------------------------
__device__ __forceinline__ u64 pack2(float lo, float hi) {
    u64 r; asm("mov.b64 %0, {%1, %2};" : "=l"(r) : "f"(lo), "f"(hi)); return r;
}
__device__ __forceinline__ u64 bcast2(float v) { return pack2(v, v); }
__device__ __forceinline__ float2 u2f(u64 v) {
    float2 r; asm("mov.b64 {%0, %1}, %2;" : "=f"(r.x), "=f"(r.y) : "l"(v)); return r;
}
__device__ __forceinline__ u64 fma2(u64 a, u64 b, u64 c) {
    u64 r; asm("fma.rn.f32x2 %0, %1, %2, %3;" : "=l"(r) : "l"(a), "l"(b), "l"(c)); return r;
}
__device__ __forceinline__ u64 mul2(u64 a, u64 b) {
    u64 r; asm("mul.rn.f32x2 %0, %1, %2;" : "=l"(r) : "l"(a), "l"(b)); return r;
}
__device__ __forceinline__ float hsum2(u64 v) {
    float2 f = u2f(v); return f.x + f.y;
}

// ---------------- scratch (static device globals; no allocation) -------------
__device__ float  g_s0[NN * FF];
__device__ float  g_s1[NN * FF];
__device__ float  g_v0[NN * 3 * FF];     // [n][k][f]
__device__ float4 g_rbf4s[EE * 2];       // bessel basis, receiver-sorted
__device__ float4 g_Y4s[EE];             // unit vector, receiver-sorted
__device__ int    g_snds[EE];            // senders, receiver-sorted
__device__ int    g_cnt[NN];             // receiver histogram
__device__ int    g_cur[NN];             // scatter cursors
__device__ int    g_off[NN + 1];         // CSR offsets
__device__ int    g_scnt[ZZ];            // species histogram
__device__ int    g_scur[ZZ];
__device__ int    g_norder[NPAD];        // species-grouped node order (-1 pad)

// ---------------- preprocessing ------------------------------------------------
__global__ void zero_sort_kernel()
{
    int i = blockIdx.x * blockDim.x + threadIdx.x;
    if (i < NN)   g_cnt[i] = 0;
    if (i < ZZ)   g_scnt[i] = 0;
    if (i < NPAD) g_norder[i] = -1;
}

__global__ void hist_kernel(const int* __restrict__ receivers,
                            const int* __restrict__ species)
{
    int i = blockIdx.x * blockDim.x + threadIdx.x;
    if (i < EE) atomicAdd(&g_cnt[receivers[i]], 1);
    if (i < NN) atomicAdd(&g_scnt[species[i]], 1);
}

__global__ void scan_kernel()   // 1 block, 1024 threads; NN = 1024*32
{
    __shared__ int part[1024];
    int tid = threadIdx.x;

    if (tid == 0) {             // tiny species scan folded in
        int off = 0;
#pragma unroll
        for (int z = 0; z < ZZ; z++) {
            g_scur[z] = off;
            off += ((g_scnt[z] + 63) / 64) * 64;
        }
    }

    int base = tid * 32;
    int loc[32];
    int sum = 0;
#pragma unroll
    for (int j = 0; j < 32; j++) { loc[j] = sum; sum += g_cnt[base + j]; }
    part[tid] = sum;
    __syncthreads();
    for (int o = 1; o < 1024; o <<= 1) {
        int v = (tid >= o) ? part[tid - o] : 0;
        __syncthreads();
        part[tid] += v;
        __syncthreads();
    }
    int pref = part[tid] - sum;
#pragma unroll
    for (int j = 0; j < 32; j++) {
        int o = pref + loc[j];
        g_off[base + j] = o;
        g_cur[base + j] = o;
    }
    if (tid == 1023) g_off[NN] = part[1023];
}

// precompute (edge scatter) + species scatter + embedding init, one launch
__global__ void fused_pre_kernel(const float* __restrict__ vectors,
                                 const float* __restrict__ embed_s,
                                 const int* __restrict__ senders,
                                 const int* __restrict__ receivers,
                                 const int* __restrict__ species)
{
    int idx = blockIdx.x * blockDim.x + threadIdx.x;   // NN*FF threads

    if (idx < NN * FF) {
        int n = idx >> 6, f = idx & 63;
        g_s0[idx] = embed_s[species[n] * FF + f];
    }

    if (idx < EE) {
        float x = vectors[idx * 3 + 0];
        float y = vectors[idx * 3 + 1];
        float z = vectors[idx * 3 + 2];
        float r2 = x * x + y * y + z * z + 1e-12f;
        float r  = sqrtf(r2);
        float inv = 1.0f / r;
        float rc = fmaxf(r, 1e-6f);
        float r6 = r2 * r2 * r2;
        float env = 1.0f - 28.0f * r6 + 48.0f * r6 * r - 21.0f * r6 * r2;
        if (r >= 1.0f) env = 0.0f;
        float kk = env * 1.4142135623730951f / rc;
        float pr = 3.14159265358979323846f * rc;
        float rb[NBB];
#pragma unroll
        for (int n2 = 1; n2 <= NBB; n2++)
            rb[n2 - 1] = kk * __sinf((float)n2 * pr);

        int pos = atomicAdd(&g_cur[receivers[idx]], 1);
        g_Y4s[pos] = make_float4(x * inv, y * inv, z * inv, 0.f);
        g_rbf4s[pos * 2 + 0] = make_float4(rb[0], rb[1], rb[2], rb[3]);
        g_rbf4s[pos * 2 + 1] = make_float4(rb[4], rb[5], rb[6], rb[7]);
        g_snds[pos] = senders[idx];
    }

    if (idx < NN) {
        int pos = atomicAdd(&g_scur[species[idx]], 1);
        g_norder[pos] = idx;
    }
}

// ---------------- fused per-layer kernel ---------------------------------------
// One warp per node: CSR edge reduce (f32x2, f-pairs) -> shared stage ->
// f-packed matvecs (no broadcast MOVs) + product basis + skip + readout.
//
// Shared layout (floats):
//   [0,4096)      pW1: Wls    packed-over-f (u64[2048])
//   [4096,8192)   pW2: Wlv    packed
//   [8192,12288)  pW3: Wps    packed
//   [12288,16384) pW4: ITER0 Wpv / ITER1 skip_s   packed
//   [16384,18944) sWr: radial weights (2560)
//   [18944, ...)  stage: 8 warps x STG
#define SMEM_L0 ((16384 + 2560 + 8 * 256) * 4)   /* 84 KB  */
#define SMEM_L1 ((16384 + 2560 + 8 * 384) * 4)   /* 88 KB  */

template <int ITER>
__global__ void __launch_bounds__(256, 2)
layer_kernel(const float* __restrict__ Wr_i,     // [8,320] this layer
             const float* __restrict__ Wls, const float* __restrict__ Wlv,
             const float* __restrict__ Wps,
             const float* __restrict__ Wpv,      // ITER0 only
             const float* __restrict__ skip_s,   // ITER1 only
             const int* __restrict__ species,
             const float* __restrict__ pw_i,     // [Z,9,F] this layer
             const float* __restrict__ Wread0,   // ITER0 only
             const float* __restrict__ Wr1a, const float* __restrict__ Wr1b,
             float* __restrict__ out)
{
    int spec_blk = 0;
    if (ITER == 1) {
        int n0 = g_norder[blockIdx.x * 64];
        if (n0 < 0) return;                 // fully-padded block
        spec_blk = species[n0];             // uniform for the whole block
    }

    extern __shared__ float sm[];
    u64* pW1 = (u64*)sm;
    u64* pW2 = (u64*)(sm + 4096);
    u64* pW3 = (u64*)(sm + 8192);
    u64* pW4 = (u64*)(sm + 12288);
    float* sWr = sm + 16384;
    float* sStageBase = sm + 18944;
    const int STG = (ITER == 0) ? 256 : 384;

    // ---- repack weights over f-pairs: pW[f2*64+g] = (W[2f2][g], W[2f2+1][g]) ----
    {
        const float* W4src = (ITER == 0) ? Wpv : (skip_s + spec_blk * 4096);
        for (int i = threadIdx.x; i < 2048; i += 256) {
            int f2 = i >> 6, g = i & 63;
            int r0 = (2 * f2) * 64 + g, r1 = r0 + 64;
            pW1[i] = pack2(Wls[r0], Wls[r1]);
            pW2[i] = pack2(Wlv[r0], Wlv[r1]);
            pW3[i] = pack2(Wps[r0], Wps[r1]);
            pW4[i] = pack2(W4src[r0], W4src[r1]);
        }
    }
    for (int i = threadIdx.x; i < 5 * NBB * 64; i += 256) {
        int p = i >> 9, b = (i >> 6) & 7, f = i & 63;
        sWr[i] = Wr_i[b * 320 + p * 64 + f];
    }
    __syncthreads();

    int wid  = threadIdx.x >> 5;
    int t    = threadIdx.x & 31;       // f-pair (edge phase) / lane
    int go   = 2 * t;                  // output pair (node phase)

    float* stA  = sStageBase + wid * STG;  // 64:  agg_s / ps / staged sn
    float* stV  = stA + 64;                // 192: agg_v / pv
    float* stS  = stA + 256;               // 64:  old s (ITER1)

    const float* sIn = (ITER == 0) ? g_s0 : g_s1;

    // per-block product-basis weights (ITER1: species uniform)
    float P1[9][2];
    if (ITER == 1) {
        const float* pbp = pw_i + spec_blk * 9 * FF + go;
#pragma unroll
        for (int r = 0; r < 9; r++) {
            float2 tmp = *(const float2*)&pbp[r * 64];
            P1[r][0] = tmp.x; P1[r][1] = tmp.y;
        }
    }

#pragma unroll 1
    for (int chunk = 0; chunk < 8; chunk++) {
        int n;
        if (ITER == 0) {
            n = blockIdx.x * 64 + chunk * 8 + wid;
        } else {
            n = g_norder[blockIdx.x * 64 + chunk * 8 + wid];
            if (n < 0) continue;           // warp-uniform
        }

        // ---- radial weights -> registers (live only through edge phase) ----
        u64 wr0[NBB], wr1[NBB], wr2[NBB], wr3[NBB], wr4[NBB];
#pragma unroll
        for (int b = 0; b < NBB; b++) {
            wr0[b] = *(const u64*)&sWr[(0 * 8 + b) * 64 + go];
            wr2[b] = *(const u64*)&sWr[(2 * 8 + b) * 64 + go];
            if (ITER > 0) {
                wr1[b] = *(const u64*)&sWr[(1 * 8 + b) * 64 + go];
                wr3[b] = *(const u64*)&sWr[(3 * 8 + b) * 64 + go];
                wr4[b] = *(const u64*)&sWr[(4 * 8 + b) * 64 + go];
            }
        }

        // ---- edge phase: walk CSR segment, accumulate in regs ----
        int beg = g_off[n], end = g_off[n + 1];
        u64 as = 0ull, ax = 0ull, ay = 0ull, az = 0ull;

#pragma unroll 2
        for (int i = beg; i < end; i++) {
            int snd = g_snds[i];                 // uniform -> broadcast
            float4 yv  = g_Y4s[i];
            float4 rba = g_rbf4s[i * 2 + 0];
            float4 rbb = g_rbf4s[i * 2 + 1];
            float rb[NBB] = {rba.x, rba.y, rba.z, rba.w, rbb.x, rbb.y, rbb.z, rbb.w};

            u64 w0 = 0ull, w1 = 0ull, w2 = 0ull, w3 = 0ull, w4 = 0ull;
#pragma unroll
            for (int b = 0; b < NBB; b++) {
                u64 rb2 = bcast2(rb[b]);
                w0 = fma2(rb2, wr0[b], w0);
                w2 = fma2(rb2, wr2[b], w2);
                if (ITER > 0) {
                    w1 = fma2(rb2, wr1[b], w1);
                    w3 = fma2(rb2, wr3[b], w3);
                    w4 = fma2(rb2, wr4[b], w4);
                }
            }

            u64 ss = *(const u64*)&sIn[snd * FF + go];
            u64 y02 = bcast2(yv.x), y12 = bcast2(yv.y), y22 = bcast2(yv.z);

            if (ITER == 0) {
                as = fma2(w0, ss, as);
                u64 w2s = mul2(w2, ss);
                ax = fma2(w2s, y02, ax);
                ay = fma2(w2s, y12, ay);
                az = fma2(w2s, y22, az);
            } else {
                const float* vb = g_v0 + snd * 3 * FF + go;
                u64 vx = *(const u64*)(vb);
                u64 vy = *(const u64*)(vb + 64);
                u64 vz = *(const u64*)(vb + 128);
                u64 dot = fma2(vx, y02, fma2(vy, y12, mul2(vz, y22)));
                as = fma2(w0, ss, fma2(w1, dot, as));
                u64 ny02 = bcast2(-yv.x), ny12 = bcast2(-yv.y), ny22 = bcast2(-yv.z);
                u64 c0 = fma2(vy, y22, mul2(vz, ny12));
                u64 c1 = fma2(vz, y02, mul2(vx, ny22));
                u64 c2 = fma2(vx, y12, mul2(vy, ny02));
                u64 w2s = mul2(w2, ss);
                ax = fma2(w2s, y02, fma2(w3, vx, fma2(w4, c0, ax)));
                ay = fma2(w2s, y12, fma2(w3, vy, fma2(w4, c1, ay)));
                az = fma2(w2s, y22, fma2(w3, vz, fma2(w4, c2, az)));
            }
        }

        // ---- stage edge results (+EPS) and skip input ----
        {
            float2 fs = u2f(as), fx = u2f(ax), fy = u2f(ay), fz = u2f(az);
            *(float2*)&stA[go]       = make_float2(fs.x * EPS_SC, fs.y * EPS_SC);
            *(float2*)&stV[go]       = make_float2(fx.x * EPS_SC, fx.y * EPS_SC);
            *(float2*)&stV[64 + go]  = make_float2(fy.x * EPS_SC, fy.y * EPS_SC);
            *(float2*)&stV[128 + go] = make_float2(fz.x * EPS_SC, fz.y * EPS_SC);
        }
        if (ITER > 0)
            *(float2*)&stS[go] = *(const float2*)&g_s1[n * FF + go];
        __syncwarp();

        // ---- matvec 1 (f-packed: no broadcasts) ----
        u64 aS0 = 0ull, aS1 = 0ull, aX0 = 0ull, aX1 = 0ull;
        u64 aY0 = 0ull, aY1 = 0ull, aZ0 = 0ull, aZ1 = 0ull;
        u64 aK0 = 0ull, aK1 = 0ull;
#pragma unroll 4
        for (int f2 = 0; f2 < 32; f2++) {
            u64 vA = *(const u64*)&stA[2 * f2];
            u64 vX = *(const u64*)&stV[2 * f2];
            u64 vY = *(const u64*)&stV[64 + 2 * f2];
            u64 vZ = *(const u64*)&stV[128 + 2 * f2];
            ulonglong2 wls = *(const ulonglong2*)&pW1[f2 * 64 + go];
            ulonglong2 wlv = *(const ulonglong2*)&pW2[f2 * 64 + go];
            aS0 = fma2(vA, wls.x, aS0);  aS1 = fma2(vA, wls.y, aS1);
            aX0 = fma2(vX, wlv.x, aX0);  aX1 = fma2(vX, wlv.y, aX1);
            aY0 = fma2(vY, wlv.x, aY0);  aY1 = fma2(vY, wlv.y, aY1);
            aZ0 = fma2(vZ, wlv.x, aZ0);  aZ1 = fma2(vZ, wlv.y, aZ1);
            if (ITER > 0) {
                u64 vSi = *(const u64*)&stS[2 * f2];
                ulonglong2 wks = *(const ulonglong2*)&pW4[f2 * 64 + go];
                aK0 = fma2(vSi, wks.x, aK0);  aK1 = fma2(vSi, wks.y, aK1);
            }
        }

        float svv[2] = {hsum2(aS0), hsum2(aS1)};
        float vvx[2] = {hsum2(aX0), hsum2(aX1)};
        float vvy[2] = {hsum2(aY0), hsum2(aY1)};
        float vvz[2] = {hsum2(aZ0), hsum2(aZ1)};
        float sk[2]  = {hsum2(aK0), hsum2(aK1)};

        // ---- product basis (2 outputs) ----
        float q[9][2];
        if (ITER == 0) {
            const float* pbp = pw_i + species[n] * 9 * FF + go;
#pragma unroll
            for (int r = 0; r < 9; r++) {
                float2 tmp = *(const float2*)&pbp[r * 64];
                q[r][0] = tmp.x; q[r][1] = tmp.y;
            }
        } else {
#pragma unroll
            for (int r = 0; r < 9; r++) { q[r][0] = P1[r][0]; q[r][1] = P1[r][1]; }
        }

        float ps[2], pc[2];
#pragma unroll
        for (int k = 0; k < 2; k++) {
            float vv = vvx[k]*vvx[k] + vvy[k]*vvy[k] + vvz[k]*vvz[k];
            float sq = svv[k]*svv[k];
            ps[k] = q[0][k]*svv[k] + q[1][k]*sq + q[2][k]*vv + q[3][k]*sq*svv[k] + q[4][k]*svv[k]*vv;
            pc[k] = q[5][k] + q[6][k]*svv[k] + q[7][k]*sq + q[8][k]*vv;
        }

        __syncwarp();
        *(float2*)&stA[go] = make_float2(ps[0], ps[1]);
        if (ITER == 0) {
            *(float2*)&stV[go]       = make_float2(pc[0]*vvx[0], pc[1]*vvx[1]);
            *(float2*)&stV[64 + go]  = make_float2(pc[0]*vvy[0], pc[1]*vvy[1]);
            *(float2*)&stV[128 + go] = make_float2(pc[0]*vvz[0], pc[1]*vvz[1]);
        }
        __syncwarp();

        // ---- matvec 2 (f-packed) ----
        u64 tS0 = 0ull, tS1 = 0ull;
        u64 tX0 = 0ull, tX1 = 0ull, tY0 = 0ull, tY1 = 0ull, tZ0 = 0ull, tZ1 = 0ull;
#pragma unroll 4
        for (int f2 = 0; f2 < 32; f2++) {
            u64 vA = *(const u64*)&stA[2 * f2];
            ulonglong2 wps = *(const ulonglong2*)&pW3[f2 * 64 + go];
            tS0 = fma2(vA, wps.x, tS0);  tS1 = fma2(vA, wps.y, tS1);
            if (ITER == 0) {
                u64 vX = *(const u64*)&stV[2 * f2];
                u64 vY = *(const u64*)&stV[64 + 2 * f2];
                u64 vZ = *(const u64*)&stV[128 + 2 * f2];
                ulonglong2 wpv = *(const ulonglong2*)&pW4[f2 * 64 + go];
                tX0 = fma2(vX, wpv.x, tX0);  tX1 = fma2(vX, wpv.y, tX1);
                tY0 = fma2(vY, wpv.x, tY0);  tY1 = fma2(vY, wpv.y, tY1);
                tZ0 = fma2(vZ, wpv.x, tZ0);  tZ1 = fma2(vZ, wpv.y, tZ1);
            }
        }

        float sn[2] = {hsum2(tS0), hsum2(tS1)};
        if (ITER > 0) { sn[0] += sk[0]; sn[1] += sk[1]; }

        if (ITER == 0) {
            // outputs feed layer 1
            *(float2*)&g_s1[n * FF + go] = make_float2(sn[0], sn[1]);
            float* vo = g_v0 + n * 3 * FF;
            *(float2*)&vo[go]       = make_float2(hsum2(tX0), hsum2(tX1));
            *(float2*)&vo[64 + go]  = make_float2(hsum2(tY0), hsum2(tY1));
            *(float2*)&vo[128 + go] = make_float2(hsum2(tZ0), hsum2(tZ1));

            // linear readout
            float2 wr = *(const float2*)&Wread0[go];
            float tt = sn[0] * wr.x + sn[1] * wr.y;
#pragma unroll
            for (int o = 16; o > 0; o >>= 1)
                tt += __shfl_xor_sync(0xffffffffu, tt, o);
            if (t == 0) out[n * LL + 0] = tt;
        } else {
            // nonlinear readout
            __syncwarp();
            *(float2*)&stA[go] = make_float2(sn[0], sn[1]);
            __syncwarp();
            float tt = 0.f;
            if (t < HH) {
                float h = 0.f;
#pragma unroll
                for (int f4 = 0; f4 < FF; f4 += 4) {
                    float aa[4];
                    *(float4*)aa = *(const float4*)&stA[f4];
#pragma unroll
                    for (int j = 0; j < 4; j++)
                        h = fmaf(aa[j], Wr1a[(f4 + j) * HH + t], h);
                }
                h = h / (1.0f + expf(-h));  // silu
                tt = h * Wr1b[t];
            }
#pragma unroll
            for (int o = 16; o > 0; o >>= 1)
                tt += __shfl_xor_sync(0xffffffffu, tt, o);
            if (t == 0) out[n * LL + 1] = tt;
        }
        __syncwarp();
    }
}

// ---------------- host launch -------------------------------------------------
extern "C" void kernel_launch(void* const* d_in, const int* in_sizes, int n_in,
                              void* d_out, int out_size)
{
    const float* vectors  = (const float*)d_in[0];
    const float* embed_s  = (const float*)d_in[1];
    const float* Wr       = (const float*)d_in[2];   // [2,8,320]
    const float* Wls      = (const float*)d_in[3];   // [2,64,64]
    const float* Wlv      = (const float*)d_in[4];
    const float* skip_s   = (const float*)d_in[5];   // [10,64,64]
    const float* skip_v   = (const float*)d_in[6];   // (dead: layer-1 v unused)
    const float* pw       = (const float*)d_in[7];   // [2,10,9,64]
    const float* Wps      = (const float*)d_in[8];
    const float* Wpv      = (const float*)d_in[9];
    const float* Wread0   = (const float*)d_in[10];  // [64,1]
    const float* Wr1a     = (const float*)d_in[11];  // [64,16]
    const float* Wr1b     = (const float*)d_in[12];  // [16,1]
    const int*   senders  = (const int*)d_in[13];
    const int*   receivers= (const int*)d_in[14];
    const int*   species  = (const int*)d_in[15];
    float* out = (float*)d_out;
    (void)skip_v;

    static bool attr_done = false;
    if (!attr_done) {
        cudaFuncSetAttribute((const void*)layer_kernel<0>,
                             cudaFuncAttributeMaxDynamicSharedMemorySize, SMEM_L0);
        cudaFuncSetAttribute((const void*)layer_kernel<1>,
                             cudaFuncAttributeMaxDynamicSharedMemorySize, SMEM_L1);
        attr_done = true;
    }

    // ---- preprocessing: 4 launches ----
    zero_sort_kernel<<<(NPAD + 255) / 256, 256>>>();
    hist_kernel<<<EE / 256, 256>>>(receivers, species);
    scan_kernel<<<1, 1024>>>();
    fused_pre_kernel<<<(NN * FF) / 256, 256>>>(vectors, embed_s, senders,
                                               receivers, species);

    // ---- layer 0 (fused edge reduce + node update + linear readout) ----
    layer_kernel<0><<<NN / 64, 256, SMEM_L0>>>(
        Wr, Wls, Wlv, Wps, Wpv, nullptr,
        species, pw, Wread0, nullptr, nullptr, out);

    // ---- layer 1 (species-grouped; fused; nonlinear readout) ----
    layer_kernel<1><<<NPAD / 64, 256, SMEM_L1>>>(
        Wr + NBB * 5 * FF, Wls + FF * FF, Wlv + FF * FF, Wps + FF * FF,
        nullptr, skip_s,
        species, pw + ZZ * 9 * FF, nullptr, Wr1a, Wr1b, out);
}

// round 12
// speedup vs baseline: 1.3402x; 1.0011x over previous
#include <cuda_runtime.h>
#include <cuda_bf16.h>
#include <math.h>

#define NN 32768
#define EE 262144
#define FF 64
#define ZZ 10
#define NBB 8
#define LL 2
#define HH 16
#define NPAD (NN + 64 * ZZ)              /* species-padded node ordering */
#define EPS_SC 0.24253562503633297f      /* 1/sqrt(17) */

typedef unsigned long long u64;

// ---------------- packed fp32x2 helpers ----------------------------------------
__device__ __forceinline__ u64 pack2(float lo, float hi) {
    u64 r; asm("mov.b64 %0, {%1, %2};" : "=l"(r) : "f"(lo), "f"(hi)); return r;
}
__device__ __forceinline__ u64 bcast2(float v) { return pack2(v, v); }
__device__ __forceinline__ float2 u2f(u64 v) {
    float2 r; asm("mov.b64 {%0, %1}, %2;" : "=f"(r.x), "=f"(r.y) : "l"(v)); return r;
}
__device__ __forceinline__ u64 fma2(u64 a, u64 b, u64 c) {
    u64 r; asm("fma.rn.f32x2 %0, %1, %2, %3;" : "=l"(r) : "l"(a), "l"(b), "l"(c)); return r;
}
__device__ __forceinline__ u64 mul2(u64 a, u64 b) {
    u64 r; asm("mul.rn.f32x2 %0, %1, %2;" : "=l"(r) : "l"(a), "l"(b)); return r;
}
__device__ __forceinline__ float hsum2(u64 v) {
    float2 f = u2f(v); return f.x + f.y;
}

// ---------------- scratch (static device globals; no allocation) -------------
__device__ float  g_s1[NN * FF];
__device__ float  g_v0[NN * 3 * FF];     // [n][k][f]
__device__ float4 g_rbf4s[EE * 2];       // bessel basis, receiver-sorted
__device__ float4 g_Y4s[EE];             // unit vector, receiver-sorted
__device__ int    g_snds[EE];            // sender | (sender_species << 20), sorted
__device__ int    g_cnt[NN];             // receiver histogram
__device__ int    g_cur[NN];             // scatter cursors
__device__ int    g_off[NN + 1];         // CSR offsets
__device__ int    g_scnt[ZZ];            // species histogram
__device__ int    g_scur[ZZ];
__device__ int    g_norder[NPAD];        // species-grouped node order (-1 pad)

// ---------------- preprocessing ------------------------------------------------
__global__ void zero_sort_kernel()
{
    int i = blockIdx.x * blockDim.x + threadIdx.x;
    if (i < NN)   g_cnt[i] = 0;
    if (i < ZZ)   g_scnt[i] = 0;
    if (i < NPAD) g_norder[i] = -1;
}

__global__ void hist_kernel(const int* __restrict__ receivers,
                            const int* __restrict__ species)
{
    int i = blockIdx.x * blockDim.x + threadIdx.x;
    if (i < EE) atomicAdd(&g_cnt[receivers[i]], 1);
    if (i < NN) atomicAdd(&g_scnt[species[i]], 1);
}

__global__ void scan_kernel()   // 1 block, 1024 threads; NN = 1024*32
{
    __shared__ int part[1024];
    int tid = threadIdx.x;

    if (tid == 0) {             // tiny species scan folded in
        int off = 0;
#pragma unroll
        for (int z = 0; z < ZZ; z++) {
            g_scur[z] = off;
            off += ((g_scnt[z] + 63) / 64) * 64;
        }
    }

    int base = tid * 32;
    int loc[32];
    int sum = 0;
#pragma unroll
    for (int j = 0; j < 32; j++) { loc[j] = sum; sum += g_cnt[base + j]; }
    part[tid] = sum;
    __syncthreads();
    for (int o = 1; o < 1024; o <<= 1) {
        int v = (tid >= o) ? part[tid - o] : 0;
        __syncthreads();
        part[tid] += v;
        __syncthreads();
    }
    int pref = part[tid] - sum;
#pragma unroll
    for (int j = 0; j < 32; j++) {
        int o = pref + loc[j];
        g_off[base + j] = o;
        g_cur[base + j] = o;
    }
    if (tid == 1023) g_off[NN] = part[1023];
}

// precompute (edge scatter) + species scatter, one launch
__global__ void fused_pre_kernel(const float* __restrict__ vectors,
                                 const int* __restrict__ senders,
                                 const int* __restrict__ receivers,
                                 const int* __restrict__ species)
{
    int idx = blockIdx.x * blockDim.x + threadIdx.x;   // EE threads

    if (idx < EE) {
        float x = vectors[idx * 3 + 0];
        float y = vectors[idx * 3 + 1];
        float z = vectors[idx * 3 + 2];
        float r2 = x * x + y * y + z * z + 1e-12f;
        float r  = sqrtf(r2);
        float inv = 1.0f / r;
        float rc = fmaxf(r, 1e-6f);
        float r6 = r2 * r2 * r2;
        float env = 1.0f - 28.0f * r6 + 48.0f * r6 * r - 21.0f * r6 * r2;
        if (r >= 1.0f) env = 0.0f;
        float kk = env * 1.4142135623730951f / rc;
        float pr = 3.14159265358979323846f * rc;
        float rb[NBB];
#pragma unroll
        for (int n2 = 1; n2 <= NBB; n2++)
            rb[n2 - 1] = kk * __sinf((float)n2 * pr);

        int snd = senders[idx];
        int pos = atomicAdd(&g_cur[receivers[idx]], 1);
        g_Y4s[pos] = make_float4(x * inv, y * inv, z * inv, 0.f);
        g_rbf4s[pos * 2 + 0] = make_float4(rb[0], rb[1], rb[2], rb[3]);
        g_rbf4s[pos * 2 + 1] = make_float4(rb[4], rb[5], rb[6], rb[7]);
        g_snds[pos] = snd | (species[snd] << 20);
    }

    if (idx < NN) {
        int pos = atomicAdd(&g_scur[species[idx]], 1);
        g_norder[pos] = idx;
    }
}

// ---------------- fused per-layer kernel ---------------------------------------
// One warp per node: CSR edge reduce (f32x2, f-pairs) -> shared stage ->
// f-packed matvecs + product basis + skip + readout.
//
// Shared (floats):
//   [0,4096)      pW1: Wls  packed-over-f (u64[2048])
//   [4096,8192)   pW2: Wlv  packed
//   [8192,12288)  pW3: Wps  packed
//   [12288,16384) pW4: ITER0 Wpv / ITER1 skip_s  packed
//   then sWr: radial weights (L0: 1024 floats, paths 0/2; L1: 2560 floats)
//   then stage: 8 warps x STG
#define SMEM_L0 ((16384 + 1024 + 8 * 256) * 4)   /* 76 KB  */
#define SMEM_L1 ((16384 + 2560 + 8 * 384) * 4)   /* 86 KB  */

template <int ITER>
__global__ void __launch_bounds__(256, ITER == 0 ? 3 : 2)
layer_kernel(const float* __restrict__ Wr_i,     // [8,320] this layer
             const float* __restrict__ Wls, const float* __restrict__ Wlv,
             const float* __restrict__ Wps,
             const float* __restrict__ Wpv,      // ITER0 only
             const float* __restrict__ skip_s,   // ITER1 only
             const float* __restrict__ embed_s,  // ITER0 only [Z,F]
             const int* __restrict__ species,
             const float* __restrict__ pw_i,     // [Z,9,F] this layer
             const float* __restrict__ Wread0,   // ITER0 only
             const float* __restrict__ Wr1a, const float* __restrict__ Wr1b,
             float* __restrict__ out)
{
    int spec_blk = 0;
    if (ITER == 1) {
        int n0 = g_norder[blockIdx.x * 64];
        if (n0 < 0) return;                 // fully-padded block
        spec_blk = species[n0];             // uniform for the whole block
    }

    extern __shared__ float sm[];
    u64* pW1 = (u64*)sm;
    u64* pW2 = (u64*)(sm + 4096);
    u64* pW3 = (u64*)(sm + 8192);
    u64* pW4 = (u64*)(sm + 12288);
    float* sWr = sm + 16384;
    float* sStageBase = (ITER == 0) ? (sm + 16384 + 1024) : (sm + 16384 + 2560);
    const int STG = (ITER == 0) ? 256 : 384;

    // ---- repack weights over f-pairs: pW[f2*64+g] = (W[2f2][g], W[2f2+1][g]) ----
    {
        const float* W4src = (ITER == 0) ? Wpv : (skip_s + spec_blk * 4096);
        for (int i = threadIdx.x; i < 2048; i += 256) {
            int f2 = i >> 6, g = i & 63;
            int r0 = (2 * f2) * 64 + g, r1 = r0 + 64;
            pW1[i] = pack2(Wls[r0], Wls[r1]);
            pW2[i] = pack2(Wlv[r0], Wlv[r1]);
            pW3[i] = pack2(Wps[r0], Wps[r1]);
            pW4[i] = pack2(W4src[r0], W4src[r1]);
        }
    }
    if (ITER == 0) {
        // only radial paths 0 and 2 exist in layer 0
        for (int i = threadIdx.x; i < 2 * NBB * 64; i += 256) {
            int p = i >> 9, b = (i >> 6) & 7, f = i & 63;
            sWr[i] = Wr_i[b * 320 + (p ? 128 : 0) + f];
        }
    } else {
        for (int i = threadIdx.x; i < 5 * NBB * 64; i += 256) {
            int p = i >> 9, b = (i >> 6) & 7, f = i & 63;
            sWr[i] = Wr_i[b * 320 + p * 64 + f];
        }
    }
    __syncthreads();

    int wid  = threadIdx.x >> 5;
    int t    = threadIdx.x & 31;       // f-pair (edge phase) / lane
    int go   = 2 * t;                  // output pair (node phase)

    float* stA  = sStageBase + wid * STG;  // 64:  agg_s / ps / staged sn
    float* stV  = stA + 64;                // 192: agg_v / pv
    float* stS  = stA + 256;               // 64:  old s (ITER1)

    // per-block product-basis weights (ITER1: species uniform)
    float P1[9][2];
    if (ITER == 1) {
        const float* pbp = pw_i + spec_blk * 9 * FF + go;
#pragma unroll
        for (int r = 0; r < 9; r++) {
            float2 tmp = *(const float2*)&pbp[r * 64];
            P1[r][0] = tmp.x; P1[r][1] = tmp.y;
        }
    }

#pragma unroll 1
    for (int chunk = 0; chunk < 8; chunk++) {
        int n;
        if (ITER == 0) {
            n = blockIdx.x * 64 + chunk * 8 + wid;
        } else {
            n = g_norder[blockIdx.x * 64 + chunk * 8 + wid];
            if (n < 0) continue;           // warp-uniform
        }

        // ---- radial weights -> registers (live only through edge phase) ----
        u64 wr0[NBB], wr1[NBB], wr2[NBB], wr3[NBB], wr4[NBB];
#pragma unroll
        for (int b = 0; b < NBB; b++) {
            if (ITER == 0) {
                wr0[b] = *(const u64*)&sWr[b * 64 + go];
                wr2[b] = *(const u64*)&sWr[512 + b * 64 + go];
            } else {
                wr0[b] = *(const u64*)&sWr[(0 * 8 + b) * 64 + go];
                wr1[b] = *(const u64*)&sWr[(1 * 8 + b) * 64 + go];
                wr2[b] = *(const u64*)&sWr[(2 * 8 + b) * 64 + go];
                wr3[b] = *(const u64*)&sWr[(3 * 8 + b) * 64 + go];
                wr4[b] = *(const u64*)&sWr[(4 * 8 + b) * 64 + go];
            }
        }

        // ---- edge phase: walk CSR segment, accumulate in regs ----
        int beg = g_off[n], end = g_off[n + 1];
        u64 as = 0ull, ax = 0ull, ay = 0ull, az = 0ull;

        if (ITER == 0) {
#pragma unroll 4
            for (int i = beg; i < end; i++) {
                int sv_ = g_snds[i];
                int spec = sv_ >> 20;                // sender species
                float4 yv  = g_Y4s[i];
                float4 rba = g_rbf4s[i * 2 + 0];
                float4 rbb = g_rbf4s[i * 2 + 1];
                float rb[NBB] = {rba.x, rba.y, rba.z, rba.w, rbb.x, rbb.y, rbb.z, rbb.w};

                u64 w0 = 0ull, w2 = 0ull;
#pragma unroll
                for (int b = 0; b < NBB; b++) {
                    u64 rb2 = bcast2(rb[b]);
                    w0 = fma2(rb2, wr0[b], w0);
                    w2 = fma2(rb2, wr2[b], w2);
                }

                // s0[snd] == embed_s[species[snd]] — 10 hot rows, no big gather
                u64 ss = *(const u64*)&embed_s[spec * FF + go];
                as = fma2(w0, ss, as);
                u64 w2s = mul2(w2, ss);
                ax = fma2(w2s, bcast2(yv.x), ax);
                ay = fma2(w2s, bcast2(yv.y), ay);
                az = fma2(w2s, bcast2(yv.z), az);
            }
        } else {
#pragma unroll 2
            for (int i = beg; i < end; i++) {
                int snd = g_snds[i] & 0xFFFFF;
                float4 yv  = g_Y4s[i];
                float4 rba = g_rbf4s[i * 2 + 0];
                float4 rbb = g_rbf4s[i * 2 + 1];
                float rb[NBB] = {rba.x, rba.y, rba.z, rba.w, rbb.x, rbb.y, rbb.z, rbb.w};

                u64 w0 = 0ull, w1 = 0ull, w2 = 0ull, w3 = 0ull, w4 = 0ull;
#pragma unroll
                for (int b = 0; b < NBB; b++) {
                    u64 rb2 = bcast2(rb[b]);
                    w0 = fma2(rb2, wr0[b], w0);
                    w1 = fma2(rb2, wr1[b], w1);
                    w2 = fma2(rb2, wr2[b], w2);
                    w3 = fma2(rb2, wr3[b], w3);
                    w4 = fma2(rb2, wr4[b], w4);
                }

                u64 ss = *(const u64*)&g_s1[snd * FF + go];
                u64 y02 = bcast2(yv.x), y12 = bcast2(yv.y), y22 = bcast2(yv.z);
                const float* vb = g_v0 + snd * 3 * FF + go;
                u64 vx = *(const u64*)(vb);
                u64 vy = *(const u64*)(vb + 64);
                u64 vz = *(const u64*)(vb + 128);
                u64 dot = fma2(vx, y02, fma2(vy, y12, mul2(vz, y22)));
                as = fma2(w0, ss, fma2(w1, dot, as));
                u64 ny02 = bcast2(-yv.x), ny12 = bcast2(-yv.y), ny22 = bcast2(-yv.z);
                u64 c0 = fma2(vy, y22, mul2(vz, ny12));
                u64 c1 = fma2(vz, y02, mul2(vx, ny22));
                u64 c2 = fma2(vx, y12, mul2(vy, ny02));
                u64 w2s = mul2(w2, ss);
                ax = fma2(w2s, y02, fma2(w3, vx, fma2(w4, c0, ax)));
                ay = fma2(w2s, y12, fma2(w3, vy, fma2(w4, c1, ay)));
                az = fma2(w2s, y22, fma2(w3, vz, fma2(w4, c2, az)));
            }
        }

        // ---- stage edge results (+EPS) and skip input ----
        {
            float2 fs = u2f(as), fx = u2f(ax), fy = u2f(ay), fz = u2f(az);
            *(float2*)&stA[go]       = make_float2(fs.x * EPS_SC, fs.y * EPS_SC);
            *(float2*)&stV[go]       = make_float2(fx.x * EPS_SC, fx.y * EPS_SC);
            *(float2*)&stV[64 + go]  = make_float2(fy.x * EPS_SC, fy.y * EPS_SC);
            *(float2*)&stV[128 + go] = make_float2(fz.x * EPS_SC, fz.y * EPS_SC);
        }
        if (ITER > 0)
            *(float2*)&stS[go] = *(const float2*)&g_s1[n * FF + go];
        __syncwarp();

        // ---- matvec 1 (f-packed: no broadcasts) ----
        u64 aS0 = 0ull, aS1 = 0ull, aX0 = 0ull, aX1 = 0ull;
        u64 aY0 = 0ull, aY1 = 0ull, aZ0 = 0ull, aZ1 = 0ull;
        u64 aK0 = 0ull, aK1 = 0ull;
#pragma unroll 4
        for (int f2 = 0; f2 < 32; f2++) {
            u64 vA = *(const u64*)&stA[2 * f2];
            u64 vX = *(const u64*)&stV[2 * f2];
            u64 vY = *(const u64*)&stV[64 + 2 * f2];
            u64 vZ = *(const u64*)&stV[128 + 2 * f2];
            ulonglong2 wls = *(const ulonglong2*)&pW1[f2 * 64 + go];
            ulonglong2 wlv = *(const ulonglong2*)&pW2[f2 * 64 + go];
            aS0 = fma2(vA, wls.x, aS0);  aS1 = fma2(vA, wls.y, aS1);
            aX0 = fma2(vX, wlv.x, aX0);  aX1 = fma2(vX, wlv.y, aX1);
            aY0 = fma2(vY, wlv.x, aY0);  aY1 = fma2(vY, wlv.y, aY1);
            aZ0 = fma2(vZ, wlv.x, aZ0);  aZ1 = fma2(vZ, wlv.y, aZ1);
            if (ITER > 0) {
                u64 vSi = *(const u64*)&stS[2 * f2];
                ulonglong2 wks = *(const ulonglong2*)&pW4[f2 * 64 + go];
                aK0 = fma2(vSi, wks.x, aK0);  aK1 = fma2(vSi, wks.y, aK1);
            }
        }

        float svv[2] = {hsum2(aS0), hsum2(aS1)};
        float vvx[2] = {hsum2(aX0), hsum2(aX1)};
        float vvy[2] = {hsum2(aY0), hsum2(aY1)};
        float vvz[2] = {hsum2(aZ0), hsum2(aZ1)};
        float sk[2]  = {hsum2(aK0), hsum2(aK1)};

        // ---- product basis (2 outputs) ----
        float q[9][2];
        if (ITER == 0) {
            const float* pbp = pw_i + species[n] * 9 * FF + go;
#pragma unroll
            for (int r = 0; r < 9; r++) {
                float2 tmp = *(const float2*)&pbp[r * 64];
                q[r][0] = tmp.x; q[r][1] = tmp.y;
            }
        } else {
#pragma unroll
            for (int r = 0; r < 9; r++) { q[r][0] = P1[r][0]; q[r][1] = P1[r][1]; }
        }

        float ps[2], pc[2];
#pragma unroll
        for (int k = 0; k < 2; k++) {
            float vv = vvx[k]*vvx[k] + vvy[k]*vvy[k] + vvz[k]*vvz[k];
            float sq = svv[k]*svv[k];
            ps[k] = q[0][k]*svv[k] + q[1][k]*sq + q[2][k]*vv + q[3][k]*sq*svv[k] + q[4][k]*svv[k]*vv;
            pc[k] = q[5][k] + q[6][k]*svv[k] + q[7][k]*sq + q[8][k]*vv;
        }

        __syncwarp();
        *(float2*)&stA[go] = make_float2(ps[0], ps[1]);
        if (ITER == 0) {
            *(float2*)&stV[go]       = make_float2(pc[0]*vvx[0], pc[1]*vvx[1]);
            *(float2*)&stV[64 + go]  = make_float2(pc[0]*vvy[0], pc[1]*vvy[1]);
            *(float2*)&stV[128 + go] = make_float2(pc[0]*vvz[0], pc[1]*vvz[1]);
        }
        __syncwarp();

        // ---- matvec 2 (f-packed) ----
        u64 tS0 = 0ull, tS1 = 0ull;
        u64 tX0 = 0ull, tX1 = 0ull, tY0 = 0ull, tY1 = 0ull, tZ0 = 0ull, tZ1 = 0ull;
#pragma unroll 4
        for (int f2 = 0; f2 < 32; f2++) {
            u64 vA = *(const u64*)&stA[2 * f2];
            ulonglong2 wps = *(const ulonglong2*)&pW3[f2 * 64 + go];
            tS0 = fma2(vA, wps.x, tS0);  tS1 = fma2(vA, wps.y, tS1);
            if (ITER == 0) {
                u64 vX = *(const u64*)&stV[2 * f2];
                u64 vY = *(const u64*)&stV[64 + 2 * f2];
                u64 vZ = *(const u64*)&stV[128 + 2 * f2];
                ulonglong2 wpv = *(const ulonglong2*)&pW4[f2 * 64 + go];
                tX0 = fma2(vX, wpv.x, tX0);  tX1 = fma2(vX, wpv.y, tX1);
                tY0 = fma2(vY, wpv.x, tY0);  tY1 = fma2(vY, wpv.y, tY1);
                tZ0 = fma2(vZ, wpv.x, tZ0);  tZ1 = fma2(vZ, wpv.y, tZ1);
            }
        }

        float sn[2] = {hsum2(tS0), hsum2(tS1)};
        if (ITER > 0) { sn[0] += sk[0]; sn[1] += sk[1]; }

        if (ITER == 0) {
            // outputs feed layer 1
            *(float2*)&g_s1[n * FF + go] = make_float2(sn[0], sn[1]);
            float* vo = g_v0 + n * 3 * FF;
            *(float2*)&vo[go]       = make_float2(hsum2(tX0), hsum2(tX1));
            *(float2*)&vo[64 + go]  = make_float2(hsum2(tY0), hsum2(tY1));
            *(float2*)&vo[128 + go] = make_float2(hsum2(tZ0), hsum2(tZ1));

            // linear readout
            float2 wr = *(const float2*)&Wread0[go];
            float tt = sn[0] * wr.x + sn[1] * wr.y;
#pragma unroll
            for (int o = 16; o > 0; o >>= 1)
                tt += __shfl_xor_sync(0xffffffffu, tt, o);
            if (t == 0) out[n * LL + 0] = tt;
        } else {
            // nonlinear readout
            __syncwarp();
            *(float2*)&stA[go] = make_float2(sn[0], sn[1]);
            __syncwarp();
            float tt = 0.f;
            if (t < HH) {
                float h = 0.f;
#pragma unroll
                for (int f4 = 0; f4 < FF; f4 += 4) {
                    float aa[4];
                    *(float4*)aa = *(const float4*)&stA[f4];
#pragma unroll
                    for (int j = 0; j < 4; j++)
                        h = fmaf(aa[j], Wr1a[(f4 + j) * HH + t], h);
                }
                h = h / (1.0f + expf(-h));  // silu
                tt = h * Wr1b[t];
            }
#pragma unroll
            for (int o = 16; o > 0; o >>= 1)
                tt += __shfl_xor_sync(0xffffffffu, tt, o);
            if (t == 0) out[n * LL + 1] = tt;
        }
        __syncwarp();
    }
}

// ---------------- host launch -------------------------------------------------
extern "C" void kernel_launch(void* const* d_in, const int* in_sizes, int n_in,
                              void* d_out, int out_size)
{
    const float* vectors  = (const float*)d_in[0];
    const float* embed_s  = (const float*)d_in[1];
    const float* Wr       = (const float*)d_in[2];   // [2,8,320]
    const float* Wls      = (const float*)d_in[3];   // [2,64,64]
    const float* Wlv      = (const float*)d_in[4];
    const float* skip_s   = (const float*)d_in[5];   // [10,64,64]
    const float* skip_v   = (const float*)d_in[6];   // (dead: layer-1 v unused)
    const float* pw       = (const float*)d_in[7];   // [2,10,9,64]
    const float* Wps      = (const float*)d_in[8];
    const float* Wpv      = (const float*)d_in[9];
    const float* Wread0   = (const float*)d_in[10];  // [64,1]
    const float* Wr1a     = (const float*)d_in[11];  // [64,16]
    const float* Wr1b     = (const float*)d_in[12];  // [16,1]
    const int*   senders  = (const int*)d_in[13];
    const int*   receivers= (const int*)d_in[14];
    const int*   species  = (const int*)d_in[15];
    float* out = (float*)d_out;
    (void)skip_v;

    static bool attr_done = false;
    if (!attr_done) {
        cudaFuncSetAttribute((const void*)layer_kernel<0>,
                             cudaFuncAttributeMaxDynamicSharedMemorySize, SMEM_L0);
        cudaFuncSetAttribute((const void*)layer_kernel<1>,
                             cudaFuncAttributeMaxDynamicSharedMemorySize, SMEM_L1);
        attr_done = true;
    }

    // ---- preprocessing: 4 launches ----
    zero_sort_kernel<<<(NPAD + 255) / 256, 256>>>();
    hist_kernel<<<EE / 256, 256>>>(receivers, species);
    scan_kernel<<<1, 1024>>>();
    fused_pre_kernel<<<EE / 256, 256>>>(vectors, senders, receivers, species);

    // ---- layer 0 (fused edge reduce + node update + linear readout) ----
    layer_kernel<0><<<NN / 64, 256, SMEM_L0>>>(
        Wr, Wls, Wlv, Wps, Wpv, nullptr, embed_s,
        species, pw, Wread0, nullptr, nullptr, out);

    // ---- layer 1 (species-grouped; fused; nonlinear readout) ----
    layer_kernel<1><<<NPAD / 64, 256, SMEM_L1>>>(
        Wr + NBB * 5 * FF, Wls + FF * FF, Wlv + FF * FF, Wps + FF * FF,
        nullptr, skip_s, nullptr,
        species, pw + ZZ * 9 * FF, nullptr, Wr1a, Wr1b, out);
}